// round 1
// baseline (speedup 1.0000x reference)
#include <cuda_runtime.h>
#include <cuda_bf16.h>
#include <math.h>

#define B_    4096
#define OBS_  4096
#define ENC_  1024
#define LAT_  512
#define L3_   1536   // 3*LAT
#define ACT_  3
#define NMAX_ 8

// ---------------- scratch (no allocations allowed) ----------------
__device__ float g_enc[B_ * ENC_];           // 16 MiB
__device__ float g_h  [B_ * LAT_];           //  8 MiB
__device__ float g_gi [B_ * NMAX_ * L3_];    // 192 MiB  (gi for all 8 steps)
__device__ float g_gh [B_ * L3_];            // 24 MiB

// ---------------- GEMM: C[M,N] = A[M,K] @ W[N,K]^T + bias, optional ReLU ----
// Both A and W are K-contiguous (row-major). BM=BN=128, BK=16, 256 thr, 8x8/thr.
template<int RELU>
__global__ __launch_bounds__(256)
void gemm_nt(const float* __restrict__ A, const float* __restrict__ W,
             const float* __restrict__ bias, float* __restrict__ C,
             int M, int N, int K)
{
    __shared__ float As[16][128];
    __shared__ float Bs[16][128];

    const int bx = blockIdx.x;          // N tile
    const int by = blockIdx.y;          // M tile
    const int t  = threadIdx.x;
    const int tx = t & 15;              // 0..15 -> 8 cols each
    const int ty = t >> 4;              // 0..15 -> 8 rows each

    const float* Ab = A + (size_t)by * 128 * K;
    const float* Wb = W + (size_t)bx * 128 * K;

    float acc[8][8];
    #pragma unroll
    for (int i = 0; i < 8; i++)
        #pragma unroll
        for (int j = 0; j < 8; j++) acc[i][j] = 0.f;

    for (int k0 = 0; k0 < K; k0 += 16) {
        // load 128x16 tiles of A and W, stored transposed (k-major in smem)
        #pragma unroll
        for (int s = 0; s < 2; s++) {
            int slot = t + s * 256;          // 0..511 float4 slots
            int row  = slot >> 2;            // 0..127
            int kv   = (slot & 3) * 4;       // 0,4,8,12
            float4 va = *(const float4*)(Ab + (size_t)row * K + k0 + kv);
            As[kv + 0][row] = va.x; As[kv + 1][row] = va.y;
            As[kv + 2][row] = va.z; As[kv + 3][row] = va.w;
            float4 vw = *(const float4*)(Wb + (size_t)row * K + k0 + kv);
            Bs[kv + 0][row] = vw.x; Bs[kv + 1][row] = vw.y;
            Bs[kv + 2][row] = vw.z; Bs[kv + 3][row] = vw.w;
        }
        __syncthreads();

        #pragma unroll
        for (int kk = 0; kk < 16; kk++) {
            float4 a0 = *(const float4*)&As[kk][ty * 8];
            float4 a1 = *(const float4*)&As[kk][ty * 8 + 4];
            float4 b0 = *(const float4*)&Bs[kk][tx * 8];
            float4 b1 = *(const float4*)&Bs[kk][tx * 8 + 4];
            float a[8] = {a0.x,a0.y,a0.z,a0.w,a1.x,a1.y,a1.z,a1.w};
            float b[8] = {b0.x,b0.y,b0.z,b0.w,b1.x,b1.y,b1.z,b1.w};
            #pragma unroll
            for (int i = 0; i < 8; i++)
                #pragma unroll
                for (int j = 0; j < 8; j++)
                    acc[i][j] = fmaf(a[i], b[j], acc[i][j]);
        }
        __syncthreads();
    }

    // epilogue
    const int col0 = bx * 128 + tx * 8;
    const int row0 = by * 128 + ty * 8;
    float bv[8];
    #pragma unroll
    for (int j = 0; j < 8; j++) bv[j] = bias[col0 + j];
    #pragma unroll
    for (int i = 0; i < 8; i++) {
        float* Cr = C + (size_t)(row0 + i) * N + col0;
        #pragma unroll
        for (int j = 0; j < 8; j++) {
            float v = acc[i][j] + bv[j];
            if (RELU) v = fmaxf(v, 0.f);
            Cr[j] = v;
        }
    }
}

// ---------------- value head: out[b] = tanh(enc[b,:] . Wv + bv) -------------
__global__ __launch_bounds__(256)
void vnet_kernel(const float* __restrict__ enc, const float* __restrict__ Wv,
                 const float* __restrict__ bv, float* __restrict__ out)
{
    __shared__ float red[8];
    const int b = blockIdx.x;
    float s = 0.f;
    for (int k = threadIdx.x; k < ENC_; k += 256)
        s = fmaf(enc[(size_t)b * ENC_ + k], Wv[k], s);
    // warp reduce
    #pragma unroll
    for (int o = 16; o > 0; o >>= 1) s += __shfl_down_sync(0xffffffff, s, o);
    if ((threadIdx.x & 31) == 0) red[threadIdx.x >> 5] = s;
    __syncthreads();
    if (threadIdx.x == 0) {
        float tot = 0.f;
        #pragma unroll
        for (int w = 0; w < 8; w++) tot += red[w];
        out[b] = tanhf(tot + bv[0]);
    }
}

// ---------------- GRU gate/mask update for step t ---------------------------
__device__ __forceinline__ float sigmoidf_(float x) { return 1.f / (1.f + expf(-x)); }

__global__ __launch_bounds__(256)
void gru_gate(const float* __restrict__ gi_all, const float* __restrict__ gh,
              const int* __restrict__ counts, float* __restrict__ h, int t)
{
    const int idx = blockIdx.x * 256 + threadIdx.x;  // over B*LAT
    const int b = idx / LAT_;
    const int j = idx - b * LAT_;
    const float* gib = gi_all + ((size_t)b * NMAX_ + t) * L3_;
    const float* ghb = gh + (size_t)b * L3_;
    float r = sigmoidf_(gib[j] + ghb[j]);
    float z = sigmoidf_(gib[LAT_ + j] + ghb[LAT_ + j]);
    float n = tanhf(gib[2 * LAT_ + j] + r * ghb[2 * LAT_ + j]);
    float hv = h[idx];
    float hn = (1.f - z) * n + z * hv;
    h[idx] = (t < counts[b]) ? hn : hv;
}

// ---------------- probs head: softmax(relu(h @ Wpr^T + bpr)) ----------------
__global__ __launch_bounds__(256)
void probs_kernel(const float* __restrict__ h, const float* __restrict__ Wpr,
                  const float* __restrict__ bpr, float* __restrict__ out)
{
    __shared__ float Ws[ACT_][LAT_];
    for (int i = threadIdx.x; i < ACT_ * LAT_; i += 256)
        Ws[i / LAT_][i % LAT_] = Wpr[i];
    __syncthreads();

    const int warp = threadIdx.x >> 5;
    const int lane = threadIdx.x & 31;
    const int b = blockIdx.x * 8 + warp;

    float a0 = 0.f, a1 = 0.f, a2 = 0.f;
    const float* hb = h + (size_t)b * LAT_;
    for (int k = lane; k < LAT_; k += 32) {
        float hv = hb[k];
        a0 = fmaf(hv, Ws[0][k], a0);
        a1 = fmaf(hv, Ws[1][k], a1);
        a2 = fmaf(hv, Ws[2][k], a2);
    }
    #pragma unroll
    for (int o = 16; o > 0; o >>= 1) {
        a0 += __shfl_down_sync(0xffffffff, a0, o);
        a1 += __shfl_down_sync(0xffffffff, a1, o);
        a2 += __shfl_down_sync(0xffffffff, a2, o);
    }
    if (lane == 0) {
        float l0 = fmaxf(a0 + bpr[0], 0.f);
        float l1 = fmaxf(a1 + bpr[1], 0.f);
        float l2 = fmaxf(a2 + bpr[2], 0.f);
        float m = fmaxf(l0, fmaxf(l1, l2));
        float e0 = expf(l0 - m), e1 = expf(l1 - m), e2 = expf(l2 - m);
        float inv = 1.f / (e0 + e1 + e2);
        out[(size_t)b * ACT_ + 0] = e0 * inv;
        out[(size_t)b * ACT_ + 1] = e1 * inv;
        out[(size_t)b * ACT_ + 2] = e2 * inv;
    }
}

// ---------------- launch ----------------------------------------------------
extern "C" void kernel_launch(void* const* d_in, const int* in_sizes, int n_in,
                              void* d_out, int out_size)
{
    const float* observation = (const float*)d_in[0];   // [B, OBS]
    const float* neighbors   = (const float*)d_in[1];   // [B, NMAX, LAT]
    const int*   counts      = (const int*)  d_in[2];   // [B]
    const float* W_ds  = (const float*)d_in[3];
    const float* b_ds  = (const float*)d_in[4];
    const float* W_pol = (const float*)d_in[5];
    const float* b_pol = (const float*)d_in[6];
    const float* W_v   = (const float*)d_in[7];
    const float* b_v   = (const float*)d_in[8];
    const float* W_ih  = (const float*)d_in[9];
    const float* b_ih  = (const float*)d_in[10];
    const float* W_hh  = (const float*)d_in[11];
    const float* b_hh  = (const float*)d_in[12];
    const float* W_pr  = (const float*)d_in[13];
    const float* b_pr  = (const float*)d_in[14];

    float* out_probs = (float*)d_out;                  // [B, 3]
    float* out_vals  = (float*)d_out + (size_t)B_ * ACT_;  // [B, 1]

    float *enc, *h, *gi, *gh;
    cudaGetSymbolAddress((void**)&enc, g_enc);
    cudaGetSymbolAddress((void**)&h,   g_h);
    cudaGetSymbolAddress((void**)&gi,  g_gi);
    cudaGetSymbolAddress((void**)&gh,  g_gh);

    // 1) enc = relu(obs @ W_ds^T + b_ds)   [4096 x 1024], K=4096
    gemm_nt<1><<<dim3(ENC_ / 128, B_ / 128), 256>>>(observation, W_ds, b_ds, enc, B_, ENC_, OBS_);

    // 2) h = relu(enc @ W_pol^T + b_pol)   [4096 x 512], K=1024
    gemm_nt<1><<<dim3(LAT_ / 128, B_ / 128), 256>>>(enc, W_pol, b_pol, h, B_, LAT_, ENC_);

    // 3) state_vals = tanh(enc @ W_v^T + b_v)
    vnet_kernel<<<B_, 256>>>(enc, W_v, b_v, out_vals);

    // 4) gi (all 8 steps at once): [B*8, 1536] = neighbors[B*8,512] @ W_ih^T + b_ih
    gemm_nt<0><<<dim3(L3_ / 128, (B_ * NMAX_) / 128), 256>>>(neighbors, W_ih, b_ih, gi, B_ * NMAX_, L3_, LAT_);

    // 5) sequential GRU: gh = h @ W_hh^T + b_hh, then gate/mask update
    for (int t = 0; t < NMAX_; t++) {
        gemm_nt<0><<<dim3(L3_ / 128, B_ / 128), 256>>>(h, W_hh, b_hh, gh, B_, L3_, LAT_);
        gru_gate<<<(B_ * LAT_) / 256, 256>>>(gi, gh, counts, h, t);
    }

    // 6) probs = softmax(relu(h @ W_pr^T + b_pr))
    probs_kernel<<<B_ / 8, 256>>>(h, W_pr, b_pr, out_probs);
}

// round 3
// speedup vs baseline: 3.0427x; 3.0427x over previous
#include <cuda_runtime.h>
#include <cuda_bf16.h>
#include <cstdint>
#include <math.h>

#define B_    4096
#define OBS_  4096
#define ENC_  1024
#define LAT_  512
#define L3_   1536   // 3*LAT
#define ACT_  3
#define NMAX_ 8

// ---------------- scratch (no allocations allowed) ----------------
__device__ float g_enc[B_ * ENC_];           // 16 MiB
__device__ float g_h  [B_ * LAT_];           //  8 MiB
__device__ float g_gi [B_ * NMAX_ * L3_];    // 192 MiB
__device__ float g_gh [B_ * L3_];            // 24 MiB

__device__ __forceinline__ uint32_t f2tf32(float x) {
    uint32_t u; asm("cvt.rna.tf32.f32 %0, %1;" : "=r"(u) : "f"(x)); return u;
}

// ============ tf32 mma.sync GEMM: C[M,N] = A[M,K] @ W[N,K]^T + bias =========
// CTA tile 128x128, 256 threads = 8 warps (4 M x 2 N), warp tile 32x64.
// K chunks of 32, double-buffered smem, [row][k] layout with +4 pad.
#define KCH   32
#define PADK  36          // 32 + 4 pad (words)
#define TILE_WORDS (128 * PADK)

template<int RELU>
__global__ __launch_bounds__(256, 1)
void gemm_mma(const float* __restrict__ A, const float* __restrict__ W,
              const float* __restrict__ bias, float* __restrict__ C,
              int N, int K)
{
    extern __shared__ uint32_t sm[];
    uint32_t* As = sm;                      // 2 buffers
    uint32_t* Bs = sm + 2 * TILE_WORDS;     // 2 buffers

    const int tid  = threadIdx.x;
    const int wid  = tid >> 5;
    const int lane = tid & 31;
    const int g    = lane >> 2;             // group 0..7
    const int t    = lane & 3;              // thread-in-group 0..3

    const int wm = wid & 3;                 // M quadrant (32 rows)
    const int wn = wid >> 2;                // N half (64 cols)

    const int n0 = blockIdx.x * 128;
    const int m0 = blockIdx.y * 128;
    const float* Ab = A + (size_t)m0 * K;
    const float* Wb = W + (size_t)n0 * K;
    const int NC = K / KCH;

    float acc[2][8][4];
    #pragma unroll
    for (int i = 0; i < 2; i++)
        #pragma unroll
        for (int j = 0; j < 8; j++)
            #pragma unroll
            for (int r = 0; r < 4; r++) acc[i][j][r] = 0.f;

    // per-thread staging for next chunk: 4 float4 of A, 4 float4 of B
    float4 ra[4], rb[4];

    // slot mapping: slot = tid + i*256 (0..1023); row = slot>>3, kq = slot&7
    auto ldg_chunk = [&](int k0) {
        #pragma unroll
        for (int i = 0; i < 4; i++) {
            int slot = tid + i * 256;
            int row = slot >> 3, kq = slot & 7;
            ra[i] = *(const float4*)(Ab + (size_t)row * K + k0 + kq * 4);
            rb[i] = *(const float4*)(Wb + (size_t)row * K + k0 + kq * 4);
        }
    };
    auto sts_chunk = [&](int s) {
        uint32_t* a = As + s * TILE_WORDS;
        uint32_t* b = Bs + s * TILE_WORDS;
        #pragma unroll
        for (int i = 0; i < 4; i++) {
            int slot = tid + i * 256;
            int row = slot >> 3, kq = slot & 7;
            uint32_t* pa = a + row * PADK + kq * 4;
            pa[0] = f2tf32(ra[i].x); pa[1] = f2tf32(ra[i].y);
            pa[2] = f2tf32(ra[i].z); pa[3] = f2tf32(ra[i].w);
            uint32_t* pb = b + row * PADK + kq * 4;
            pb[0] = f2tf32(rb[i].x); pb[1] = f2tf32(rb[i].y);
            pb[2] = f2tf32(rb[i].z); pb[3] = f2tf32(rb[i].w);
        }
    };

    ldg_chunk(0);
    sts_chunk(0);
    __syncthreads();

    for (int c = 0; c < NC; c++) {
        const int s = c & 1;
        if (c + 1 < NC) ldg_chunk((c + 1) * KCH);

        const uint32_t* a = As + s * TILE_WORDS;
        const uint32_t* b = Bs + s * TILE_WORDS;

        #pragma unroll
        for (int kk = 0; kk < 4; kk++) {
            const int kb = kk * 8;
            uint32_t af[2][4], bf[8][2];
            #pragma unroll
            for (int i = 0; i < 2; i++) {
                const int row = wm * 32 + i * 16 + g;
                af[i][0] = a[row * PADK + kb + t];
                af[i][1] = a[(row + 8) * PADK + kb + t];
                af[i][2] = a[row * PADK + kb + t + 4];
                af[i][3] = a[(row + 8) * PADK + kb + t + 4];
            }
            #pragma unroll
            for (int j = 0; j < 8; j++) {
                const int col = wn * 64 + j * 8 + g;
                bf[j][0] = b[col * PADK + kb + t];
                bf[j][1] = b[col * PADK + kb + t + 4];
            }
            #pragma unroll
            for (int i = 0; i < 2; i++)
                #pragma unroll
                for (int j = 0; j < 8; j++) {
                    asm volatile(
                        "mma.sync.aligned.m16n8k8.row.col.f32.tf32.tf32.f32 "
                        "{%0, %1, %2, %3}, {%4, %5, %6, %7}, {%8, %9}, "
                        "{%0, %1, %2, %3};"
                        : "+f"(acc[i][j][0]), "+f"(acc[i][j][1]),
                          "+f"(acc[i][j][2]), "+f"(acc[i][j][3])
                        : "r"(af[i][0]), "r"(af[i][1]), "r"(af[i][2]), "r"(af[i][3]),
                          "r"(bf[j][0]), "r"(bf[j][1]));
                }
        }

        if (c + 1 < NC) {
            sts_chunk(s ^ 1);
            __syncthreads();
        }
    }

    // ---- epilogue: bias + optional ReLU, write float2 pairs ----
    #pragma unroll
    for (int i = 0; i < 2; i++) {
        const int row = m0 + wm * 32 + i * 16 + g;
        #pragma unroll
        for (int j = 0; j < 8; j++) {
            const int col = n0 + wn * 64 + j * 8 + 2 * t;
            const float b0 = bias[col], b1 = bias[col + 1];
            float2 v0 = { acc[i][j][0] + b0, acc[i][j][1] + b1 };
            float2 v1 = { acc[i][j][2] + b0, acc[i][j][3] + b1 };
            if (RELU) {
                v0.x = fmaxf(v0.x, 0.f); v0.y = fmaxf(v0.y, 0.f);
                v1.x = fmaxf(v1.x, 0.f); v1.y = fmaxf(v1.y, 0.f);
            }
            *(float2*)(C + (size_t)row * N + col) = v0;
            *(float2*)(C + (size_t)(row + 8) * N + col) = v1;
        }
    }
}

// ---------------- value head: out[b] = tanh(enc[b,:] . Wv + bv) -------------
__global__ __launch_bounds__(256)
void vnet_kernel(const float* __restrict__ enc, const float* __restrict__ Wv,
                 const float* __restrict__ bv, float* __restrict__ out)
{
    __shared__ float red[8];
    const int b = blockIdx.x;
    float s = 0.f;
    for (int k = threadIdx.x; k < ENC_; k += 256)
        s = fmaf(enc[(size_t)b * ENC_ + k], Wv[k], s);
    #pragma unroll
    for (int o = 16; o > 0; o >>= 1) s += __shfl_down_sync(0xffffffff, s, o);
    if ((threadIdx.x & 31) == 0) red[threadIdx.x >> 5] = s;
    __syncthreads();
    if (threadIdx.x == 0) {
        float tot = 0.f;
        #pragma unroll
        for (int w = 0; w < 8; w++) tot += red[w];
        out[b] = tanhf(tot + bv[0]);
    }
}

// ---------------- GRU gate/mask update for step t ---------------------------
__device__ __forceinline__ float sigmoidf_(float x) { return 1.f / (1.f + expf(-x)); }

__global__ __launch_bounds__(256)
void gru_gate(const float* __restrict__ gi_all, const float* __restrict__ gh,
              const int* __restrict__ counts, float* __restrict__ h, int t)
{
    const int idx = blockIdx.x * 256 + threadIdx.x;  // over B*LAT
    const int b = idx / LAT_;
    const int j = idx - b * LAT_;
    const float* gib = gi_all + ((size_t)b * NMAX_ + t) * L3_;
    const float* ghb = gh + (size_t)b * L3_;
    float r = sigmoidf_(gib[j] + ghb[j]);
    float z = sigmoidf_(gib[LAT_ + j] + ghb[LAT_ + j]);
    float n = tanhf(gib[2 * LAT_ + j] + r * ghb[2 * LAT_ + j]);
    float hv = h[idx];
    float hn = (1.f - z) * n + z * hv;
    h[idx] = (t < counts[b]) ? hn : hv;
}

// ---------------- probs head: softmax(relu(h @ Wpr^T + bpr)) ----------------
__global__ __launch_bounds__(256)
void probs_kernel(const float* __restrict__ h, const float* __restrict__ Wpr,
                  const float* __restrict__ bpr, float* __restrict__ out)
{
    __shared__ float Ws[ACT_][LAT_];
    for (int i = threadIdx.x; i < ACT_ * LAT_; i += 256)
        Ws[i / LAT_][i % LAT_] = Wpr[i];
    __syncthreads();

    const int warp = threadIdx.x >> 5;
    const int lane = threadIdx.x & 31;
    const int b = blockIdx.x * 8 + warp;

    float a0 = 0.f, a1 = 0.f, a2 = 0.f;
    const float* hb = h + (size_t)b * LAT_;
    for (int k = lane; k < LAT_; k += 32) {
        float hv = hb[k];
        a0 = fmaf(hv, Ws[0][k], a0);
        a1 = fmaf(hv, Ws[1][k], a1);
        a2 = fmaf(hv, Ws[2][k], a2);
    }
    #pragma unroll
    for (int o = 16; o > 0; o >>= 1) {
        a0 += __shfl_down_sync(0xffffffff, a0, o);
        a1 += __shfl_down_sync(0xffffffff, a1, o);
        a2 += __shfl_down_sync(0xffffffff, a2, o);
    }
    if (lane == 0) {
        float l0 = fmaxf(a0 + bpr[0], 0.f);
        float l1 = fmaxf(a1 + bpr[1], 0.f);
        float l2 = fmaxf(a2 + bpr[2], 0.f);
        float m = fmaxf(l0, fmaxf(l1, l2));
        float e0 = expf(l0 - m), e1 = expf(l1 - m), e2 = expf(l2 - m);
        float inv = 1.f / (e0 + e1 + e2);
        out[(size_t)b * ACT_ + 0] = e0 * inv;
        out[(size_t)b * ACT_ + 1] = e1 * inv;
        out[(size_t)b * ACT_ + 2] = e2 * inv;
    }
}

// ---------------- launch ----------------------------------------------------
#define SMEM_BYTES (4 * TILE_WORDS * 4)   // 2 bufs x (A+B) x 128*36 words

extern "C" void kernel_launch(void* const* d_in, const int* in_sizes, int n_in,
                              void* d_out, int out_size)
{
    const float* observation = (const float*)d_in[0];   // [B, OBS]
    const float* neighbors   = (const float*)d_in[1];   // [B, NMAX, LAT]
    const int*   counts      = (const int*)  d_in[2];   // [B]
    const float* W_ds  = (const float*)d_in[3];
    const float* b_ds  = (const float*)d_in[4];
    const float* W_pol = (const float*)d_in[5];
    const float* b_pol = (const float*)d_in[6];
    const float* W_v   = (const float*)d_in[7];
    const float* b_v   = (const float*)d_in[8];
    const float* W_ih  = (const float*)d_in[9];
    const float* b_ih  = (const float*)d_in[10];
    const float* W_hh  = (const float*)d_in[11];
    const float* b_hh  = (const float*)d_in[12];
    const float* W_pr  = (const float*)d_in[13];
    const float* b_pr  = (const float*)d_in[14];

    float* out_probs = (float*)d_out;                       // [B, 3]
    float* out_vals  = (float*)d_out + (size_t)B_ * ACT_;   // [B, 1]

    float *enc, *h, *gi, *gh;
    cudaGetSymbolAddress((void**)&enc, g_enc);
    cudaGetSymbolAddress((void**)&h,   g_h);
    cudaGetSymbolAddress((void**)&gi,  g_gi);
    cudaGetSymbolAddress((void**)&gh,  g_gh);

    cudaFuncSetAttribute(gemm_mma<0>, cudaFuncAttributeMaxDynamicSharedMemorySize, SMEM_BYTES);
    cudaFuncSetAttribute(gemm_mma<1>, cudaFuncAttributeMaxDynamicSharedMemorySize, SMEM_BYTES);

    // 1) enc = relu(obs @ W_ds^T + b_ds)   [4096 x 1024], K=4096
    gemm_mma<1><<<dim3(ENC_ / 128, B_ / 128), 256, SMEM_BYTES>>>(observation, W_ds, b_ds, enc, ENC_, OBS_);

    // 2) h = relu(enc @ W_pol^T + b_pol)   [4096 x 512], K=1024
    gemm_mma<1><<<dim3(LAT_ / 128, B_ / 128), 256, SMEM_BYTES>>>(enc, W_pol, b_pol, h, LAT_, ENC_);

    // 3) state_vals = tanh(enc @ W_v^T + b_v)
    vnet_kernel<<<B_, 256>>>(enc, W_v, b_v, out_vals);

    // 4) gi (all 8 steps at once): [B*8, 1536] = neighbors[B*8,512] @ W_ih^T + b_ih
    gemm_mma<0><<<dim3(L3_ / 128, (B_ * NMAX_) / 128), 256, SMEM_BYTES>>>(neighbors, W_ih, b_ih, gi, L3_, LAT_);

    // 5) sequential GRU: gh = h @ W_hh^T + b_hh, then gate/mask update
    for (int t = 0; t < NMAX_; t++) {
        gemm_mma<0><<<dim3(L3_ / 128, B_ / 128), 256, SMEM_BYTES>>>(h, W_hh, b_hh, gh, L3_, LAT_);
        gru_gate<<<(B_ * LAT_) / 256, 256>>>(gi, gh, counts, h, t);
    }

    // 6) probs = softmax(relu(h @ W_pr^T + b_pr))
    probs_kernel<<<B_ / 8, 256>>>(h, W_pr, b_pr, out_probs);
}

// round 4
// speedup vs baseline: 3.3219x; 1.0917x over previous
#include <cuda_runtime.h>
#include <cuda_bf16.h>
#include <cstdint>
#include <math.h>

#define B_    4096
#define OBS_  4096
#define ENC_  1024
#define LAT_  512
#define L3_   1536   // 3*LAT
#define ACT_  3
#define NMAX_ 8

// ---------------- scratch (no allocations allowed) ----------------
__device__ float g_enc[B_ * ENC_];            // 16 MiB (tf32-rounded at producer)
__device__ float g_h  [B_ * LAT_];            //  8 MiB (tf32-rounded at producer)
__device__ float g_gi [B_ * NMAX_ * L3_];     // 192 MiB
__device__ float g_gh [B_ * L3_];             // 24 MiB
// tf32-rounded copies of GEMM operands
__device__ float g_obs_r [B_ * OBS_];         // 64 MiB
__device__ float g_nb_r  [B_ * NMAX_ * LAT_]; // 64 MiB
__device__ float g_Wds_r [ENC_ * OBS_];       // 16 MiB
__device__ float g_Wpol_r[LAT_ * ENC_];       //  2 MiB
__device__ float g_Wih_r [L3_ * LAT_];        //  3 MiB
__device__ float g_Whh_r [L3_ * LAT_];        //  3 MiB

__device__ __forceinline__ float rna_tf32(float x) {
    uint32_t u; asm("cvt.rna.tf32.f32 %0, %1;" : "=r"(u) : "f"(x));
    return __uint_as_float(u);
}

// ---------------- tf32 rounding pre-pass (float4 vectorized) ----------------
__global__ __launch_bounds__(256)
void round_tf32_k(const float* __restrict__ in, float* __restrict__ out, int n4)
{
    int i = blockIdx.x * 256 + threadIdx.x;
    if (i >= n4) return;
    float4 v = ((const float4*)in)[i];
    v.x = rna_tf32(v.x); v.y = rna_tf32(v.y);
    v.z = rna_tf32(v.z); v.w = rna_tf32(v.w);
    ((float4*)out)[i] = v;
}

// ============ tf32 mma.sync GEMM: C[M,N] = A[M,K] @ W[N,K]^T + bias =========
// CTA 128x128, 256 thr = 8 warps (4M x 2N), warp tile 32x64.
// K chunks of 32, 3-stage cp.async ring, [row][k] smem layout with +4 pad.
#define KCH   32
#define PADK  36
#define TILE_WORDS (128 * PADK)               // 4608 words = 18432 B
#define STAGES 3
#define SMEM_BYTES (STAGES * 2 * TILE_WORDS * 4)   // 110592 B

#define CP_ASYNC16(dst, src) \
    asm volatile("cp.async.cg.shared.global [%0], [%1], 16;" :: "r"(dst), "l"(src))
#define CP_COMMIT()  asm volatile("cp.async.commit_group;" ::: "memory")
#define CP_WAIT1()   asm volatile("cp.async.wait_group 1;" ::: "memory")

template<int RELU>   // RELU=1 also rounds output to tf32 (feeds a later GEMM)
__global__ __launch_bounds__(256, 2)
void gemm_mma(const float* __restrict__ A, const float* __restrict__ W,
              const float* __restrict__ bias, float* __restrict__ C,
              int N, int K)
{
    extern __shared__ uint32_t sm[];
    const uint32_t sbase = (uint32_t)__cvta_generic_to_shared(sm);

    const int tid  = threadIdx.x;
    const int wid  = tid >> 5;
    const int lane = tid & 31;
    const int g    = lane >> 2;
    const int t    = lane & 3;
    const int wm   = wid & 3;
    const int wn   = wid >> 2;

    const int n0 = blockIdx.x * 128;
    const int m0 = blockIdx.y * 128;
    const float* Ab = A + (size_t)m0 * K;
    const float* Wb = W + (size_t)n0 * K;
    const int NC = K / KCH;

    // per-thread cp.async slots: slot = tid + i*256, row = slot>>3, kq = slot&7
    const int row_ld = tid >> 3;        // base row for i=0 (rows advance by 32)
    const int kq_ld  = tid & 7;

    auto issue_stage = [&](int c, int s) {
        const int k0 = c * KCH;
        uint32_t a_s = sbase + (uint32_t)(s * 2 * TILE_WORDS) * 4u;
        uint32_t b_s = a_s + (uint32_t)TILE_WORDS * 4u;
        #pragma unroll
        for (int i = 0; i < 4; i++) {
            int row = row_ld + i * 32;
            uint32_t off = (uint32_t)(row * PADK + kq_ld * 4) * 4u;
            CP_ASYNC16(a_s + off, Ab + (size_t)row * K + k0 + kq_ld * 4);
            CP_ASYNC16(b_s + off, Wb + (size_t)row * K + k0 + kq_ld * 4);
        }
    };

    float acc[2][8][4];
    #pragma unroll
    for (int i = 0; i < 2; i++)
        #pragma unroll
        for (int j = 0; j < 8; j++)
            #pragma unroll
            for (int r = 0; r < 4; r++) acc[i][j][r] = 0.f;

    issue_stage(0, 0); CP_COMMIT();
    if (NC > 1) issue_stage(1, 1);
    CP_COMMIT();

    for (int c = 0; c < NC; c++) {
        const int s = c % STAGES;
        CP_WAIT1();
        __syncthreads();
        if (c + 2 < NC) issue_stage(c + 2, (c + 2) % STAGES);
        CP_COMMIT();

        const uint32_t* a = sm + s * 2 * TILE_WORDS;
        const uint32_t* b = a + TILE_WORDS;

        #pragma unroll
        for (int kk = 0; kk < 4; kk++) {
            const int kb = kk * 8;
            uint32_t af[2][4], bf[8][2];
            #pragma unroll
            for (int i = 0; i < 2; i++) {
                const int row = wm * 32 + i * 16 + g;
                af[i][0] = a[row * PADK + kb + t];
                af[i][1] = a[(row + 8) * PADK + kb + t];
                af[i][2] = a[row * PADK + kb + t + 4];
                af[i][3] = a[(row + 8) * PADK + kb + t + 4];
            }
            #pragma unroll
            for (int j = 0; j < 8; j++) {
                const int col = wn * 64 + j * 8 + g;
                bf[j][0] = b[col * PADK + kb + t];
                bf[j][1] = b[col * PADK + kb + t + 4];
            }
            #pragma unroll
            for (int i = 0; i < 2; i++)
                #pragma unroll
                for (int j = 0; j < 8; j++) {
                    asm volatile(
                        "mma.sync.aligned.m16n8k8.row.col.f32.tf32.tf32.f32 "
                        "{%0, %1, %2, %3}, {%4, %5, %6, %7}, {%8, %9}, "
                        "{%0, %1, %2, %3};"
                        : "+f"(acc[i][j][0]), "+f"(acc[i][j][1]),
                          "+f"(acc[i][j][2]), "+f"(acc[i][j][3])
                        : "r"(af[i][0]), "r"(af[i][1]), "r"(af[i][2]), "r"(af[i][3]),
                          "r"(bf[j][0]), "r"(bf[j][1]));
                }
        }
        __syncthreads();
    }

    // ---- epilogue ----
    #pragma unroll
    for (int i = 0; i < 2; i++) {
        const int row = m0 + wm * 32 + i * 16 + g;
        #pragma unroll
        for (int j = 0; j < 8; j++) {
            const int col = n0 + wn * 64 + j * 8 + 2 * t;
            const float b0 = bias[col], b1 = bias[col + 1];
            float2 v0 = { acc[i][j][0] + b0, acc[i][j][1] + b1 };
            float2 v1 = { acc[i][j][2] + b0, acc[i][j][3] + b1 };
            if (RELU) {
                v0.x = rna_tf32(fmaxf(v0.x, 0.f)); v0.y = rna_tf32(fmaxf(v0.y, 0.f));
                v1.x = rna_tf32(fmaxf(v1.x, 0.f)); v1.y = rna_tf32(fmaxf(v1.y, 0.f));
            }
            *(float2*)(C + (size_t)row * N + col) = v0;
            *(float2*)(C + (size_t)(row + 8) * N + col) = v1;
        }
    }
}

// ---------------- value head: out[b] = tanh(enc[b,:] . Wv + bv) -------------
__global__ __launch_bounds__(256)
void vnet_kernel(const float* __restrict__ enc, const float* __restrict__ Wv,
                 const float* __restrict__ bv, float* __restrict__ out)
{
    __shared__ float red[8];
    const int b = blockIdx.x;
    float s = 0.f;
    for (int k = threadIdx.x; k < ENC_; k += 256)
        s = fmaf(enc[(size_t)b * ENC_ + k], Wv[k], s);
    #pragma unroll
    for (int o = 16; o > 0; o >>= 1) s += __shfl_down_sync(0xffffffff, s, o);
    if ((threadIdx.x & 31) == 0) red[threadIdx.x >> 5] = s;
    __syncthreads();
    if (threadIdx.x == 0) {
        float tot = 0.f;
        #pragma unroll
        for (int w = 0; w < 8; w++) tot += red[w];
        out[b] = tanhf(tot + bv[0]);
    }
}

// ---------------- GRU gate/mask update for step t ---------------------------
__device__ __forceinline__ float sigmoidf_(float x) { return 1.f / (1.f + expf(-x)); }

__global__ __launch_bounds__(256)
void gru_gate(const float* __restrict__ gi_all, const float* __restrict__ gh,
              const int* __restrict__ counts, float* __restrict__ h, int t)
{
    const int idx = blockIdx.x * 256 + threadIdx.x;  // over B*LAT
    const int b = idx / LAT_;
    const int j = idx - b * LAT_;
    const float* gib = gi_all + ((size_t)b * NMAX_ + t) * L3_;
    const float* ghb = gh + (size_t)b * L3_;
    float r = sigmoidf_(gib[j] + ghb[j]);
    float z = sigmoidf_(gib[LAT_ + j] + ghb[LAT_ + j]);
    float n = tanhf(gib[2 * LAT_ + j] + r * ghb[2 * LAT_ + j]);
    float hv = h[idx];
    float hn = (1.f - z) * n + z * hv;
    h[idx] = (t < counts[b]) ? rna_tf32(hn) : hv;   // h always stays tf32-rounded
}

// ---------------- probs head: softmax(relu(h @ Wpr^T + bpr)) ----------------
__global__ __launch_bounds__(256)
void probs_kernel(const float* __restrict__ h, const float* __restrict__ Wpr,
                  const float* __restrict__ bpr, float* __restrict__ out)
{
    __shared__ float Ws[ACT_][LAT_];
    for (int i = threadIdx.x; i < ACT_ * LAT_; i += 256)
        Ws[i / LAT_][i % LAT_] = Wpr[i];
    __syncthreads();

    const int warp = threadIdx.x >> 5;
    const int lane = threadIdx.x & 31;
    const int b = blockIdx.x * 8 + warp;

    float a0 = 0.f, a1 = 0.f, a2 = 0.f;
    const float* hb = h + (size_t)b * LAT_;
    for (int k = lane; k < LAT_; k += 32) {
        float hv = hb[k];
        a0 = fmaf(hv, Ws[0][k], a0);
        a1 = fmaf(hv, Ws[1][k], a1);
        a2 = fmaf(hv, Ws[2][k], a2);
    }
    #pragma unroll
    for (int o = 16; o > 0; o >>= 1) {
        a0 += __shfl_down_sync(0xffffffff, a0, o);
        a1 += __shfl_down_sync(0xffffffff, a1, o);
        a2 += __shfl_down_sync(0xffffffff, a2, o);
    }
    if (lane == 0) {
        float l0 = fmaxf(a0 + bpr[0], 0.f);
        float l1 = fmaxf(a1 + bpr[1], 0.f);
        float l2 = fmaxf(a2 + bpr[2], 0.f);
        float m = fmaxf(l0, fmaxf(l1, l2));
        float e0 = expf(l0 - m), e1 = expf(l1 - m), e2 = expf(l2 - m);
        float inv = 1.f / (e0 + e1 + e2);
        out[(size_t)b * ACT_ + 0] = e0 * inv;
        out[(size_t)b * ACT_ + 1] = e1 * inv;
        out[(size_t)b * ACT_ + 2] = e2 * inv;
    }
}

// ---------------- launch ----------------------------------------------------
static inline void round_pass(const float* in, float* out, size_t n) {
    int n4 = (int)(n / 4);
    round_tf32_k<<<(n4 + 255) / 256, 256>>>(in, out, n4);
}

extern "C" void kernel_launch(void* const* d_in, const int* in_sizes, int n_in,
                              void* d_out, int out_size)
{
    const float* observation = (const float*)d_in[0];
    const float* neighbors   = (const float*)d_in[1];
    const int*   counts      = (const int*)  d_in[2];
    const float* W_ds  = (const float*)d_in[3];
    const float* b_ds  = (const float*)d_in[4];
    const float* W_pol = (const float*)d_in[5];
    const float* b_pol = (const float*)d_in[6];
    const float* W_v   = (const float*)d_in[7];
    const float* b_v   = (const float*)d_in[8];
    const float* W_ih  = (const float*)d_in[9];
    const float* b_ih  = (const float*)d_in[10];
    const float* W_hh  = (const float*)d_in[11];
    const float* b_hh  = (const float*)d_in[12];
    const float* W_pr  = (const float*)d_in[13];
    const float* b_pr  = (const float*)d_in[14];

    float* out_probs = (float*)d_out;                       // [B, 3]
    float* out_vals  = (float*)d_out + (size_t)B_ * ACT_;   // [B, 1]

    float *enc, *h, *gi, *gh, *obs_r, *nb_r, *Wds_r, *Wpol_r, *Wih_r, *Whh_r;
    cudaGetSymbolAddress((void**)&enc,   g_enc);
    cudaGetSymbolAddress((void**)&h,     g_h);
    cudaGetSymbolAddress((void**)&gi,    g_gi);
    cudaGetSymbolAddress((void**)&gh,    g_gh);
    cudaGetSymbolAddress((void**)&obs_r, g_obs_r);
    cudaGetSymbolAddress((void**)&nb_r,  g_nb_r);
    cudaGetSymbolAddress((void**)&Wds_r, g_Wds_r);
    cudaGetSymbolAddress((void**)&Wpol_r,g_Wpol_r);
    cudaGetSymbolAddress((void**)&Wih_r, g_Wih_r);
    cudaGetSymbolAddress((void**)&Whh_r, g_Whh_r);

    cudaFuncSetAttribute(gemm_mma<0>, cudaFuncAttributeMaxDynamicSharedMemorySize, SMEM_BYTES);
    cudaFuncSetAttribute(gemm_mma<1>, cudaFuncAttributeMaxDynamicSharedMemorySize, SMEM_BYTES);

    // 0) tf32-round all GEMM operands once
    round_pass(observation, obs_r, (size_t)B_ * OBS_);
    round_pass(neighbors,   nb_r,  (size_t)B_ * NMAX_ * LAT_);
    round_pass(W_ds,  Wds_r,  (size_t)ENC_ * OBS_);
    round_pass(W_pol, Wpol_r, (size_t)LAT_ * ENC_);
    round_pass(W_ih,  Wih_r,  (size_t)L3_ * LAT_);
    round_pass(W_hh,  Whh_r,  (size_t)L3_ * LAT_);

    // 1) enc = relu(obs @ W_ds^T + b_ds)   [4096 x 1024], K=4096
    gemm_mma<1><<<dim3(ENC_ / 128, B_ / 128), 256, SMEM_BYTES>>>(obs_r, Wds_r, b_ds, enc, ENC_, OBS_);

    // 2) h = relu(enc @ W_pol^T + b_pol)   [4096 x 512], K=1024
    gemm_mma<1><<<dim3(LAT_ / 128, B_ / 128), 256, SMEM_BYTES>>>(enc, Wpol_r, b_pol, h, LAT_, ENC_);

    // 3) state_vals = tanh(enc @ W_v^T + b_v)
    vnet_kernel<<<B_, 256>>>(enc, W_v, b_v, out_vals);

    // 4) gi (all 8 steps): [B*8, 1536] = neighbors[B*8,512] @ W_ih^T + b_ih
    gemm_mma<0><<<dim3(L3_ / 128, (B_ * NMAX_) / 128), 256, SMEM_BYTES>>>(nb_r, Wih_r, b_ih, gi, L3_, LAT_);

    // 5) sequential GRU
    for (int t = 0; t < NMAX_; t++) {
        gemm_mma<0><<<dim3(L3_ / 128, B_ / 128), 256, SMEM_BYTES>>>(h, Whh_r, b_hh, gh, L3_, LAT_);
        gru_gate<<<(B_ * LAT_) / 256, 256>>>(gi, gh, counts, h, t);
    }

    // 6) probs = softmax(relu(h @ W_pr^T + b_pr))
    probs_kernel<<<B_ / 8, 256>>>(h, W_pr, b_pr, out_probs);
}

// round 5
// speedup vs baseline: 3.4271x; 1.0317x over previous
#include <cuda_runtime.h>
#include <cuda_bf16.h>
#include <cstdint>
#include <math.h>

#define B_    4096
#define OBS_  4096
#define ENC_  1024
#define LAT_  512
#define L3_   1536   // 3*LAT
#define ACT_  3
#define NMAX_ 8

// ---------------- scratch (no allocations allowed) ----------------
__device__ float g_enc[B_ * ENC_];            // tf32-rounded at producer
__device__ float g_h  [B_ * LAT_];            // tf32-rounded at producer
__device__ float g_gi [B_ * NMAX_ * L3_];
__device__ float g_gh [B_ * L3_];
// tf32-rounded copies of GEMM operands
__device__ float g_obs_r [B_ * OBS_];
__device__ float g_nb_r  [B_ * NMAX_ * LAT_];
__device__ float g_Wds_r [ENC_ * OBS_];
__device__ float g_Wpol_r[LAT_ * ENC_];
__device__ float g_Wih_r [L3_ * LAT_];
__device__ float g_Whh_r [L3_ * LAT_];

__device__ __forceinline__ float rna_tf32(float x) {
    uint32_t u; asm("cvt.rna.tf32.f32 %0, %1;" : "=r"(u) : "f"(x));
    return __uint_as_float(u);
}

// ---------------- tf32 rounding pre-pass (float4 vectorized) ----------------
__global__ __launch_bounds__(256)
void round_tf32_k(const float* __restrict__ in, float* __restrict__ out, int n4)
{
    int i = blockIdx.x * 256 + threadIdx.x;
    if (i >= n4) return;
    float4 v = ((const float4*)in)[i];
    v.x = rna_tf32(v.x); v.y = rna_tf32(v.y);
    v.z = rna_tf32(v.z); v.w = rna_tf32(v.w);
    ((float4*)out)[i] = v;
}

// ============ tf32 mma.sync GEMM: C[M,N] = A[M,K] @ W[N,K]^T + bias =========
// CTA 128x128, 128 thr = 4 warps (2M x 2N), warp tile 64x64 (crossbar-balanced:
// per warp-k8: 32 LDS feed 32 HMMA). K chunks of 32, 3-stage cp.async ring.
#define KCH   32
#define PADK  36
#define TILE_WORDS (128 * PADK)               // 4608 words = 18432 B
#define STAGES 3
#define SMEM_BYTES (STAGES * 2 * TILE_WORDS * 4)   // 110592 B

#define CP_ASYNC16(dst, src) \
    asm volatile("cp.async.cg.shared.global [%0], [%1], 16;" :: "r"(dst), "l"(src))
#define CP_COMMIT()  asm volatile("cp.async.commit_group;" ::: "memory")
#define CP_WAIT1()   asm volatile("cp.async.wait_group 1;" ::: "memory")

template<int RELU>   // RELU=1 also rounds output to tf32 (feeds a later GEMM)
__global__ __launch_bounds__(128, 2)
void gemm_mma(const float* __restrict__ A, const float* __restrict__ W,
              const float* __restrict__ bias, float* __restrict__ C,
              int N, int K)
{
    extern __shared__ uint32_t sm[];
    const uint32_t sbase = (uint32_t)__cvta_generic_to_shared(sm);

    const int tid  = threadIdx.x;
    const int wid  = tid >> 5;
    const int lane = tid & 31;
    const int g    = lane >> 2;
    const int t    = lane & 3;
    const int wm   = wid & 1;          // M half (64 rows)
    const int wn   = wid >> 1;         // N half (64 cols)

    const int n0 = blockIdx.x * 128;
    const int m0 = blockIdx.y * 128;
    const float* Ab = A + (size_t)m0 * K;
    const float* Wb = W + (size_t)n0 * K;
    const int NC = K / KCH;

    // cp.async slots: slot = tid + i*128 (0..1023), row = slot>>3, kq = slot&7
    const int row_ld = tid >> 3;       // base row (advances by 16 per i)
    const int kq_ld  = tid & 7;

    auto issue_stage = [&](int c, int s) {
        const int k0 = c * KCH;
        uint32_t a_s = sbase + (uint32_t)(s * 2 * TILE_WORDS) * 4u;
        uint32_t b_s = a_s + (uint32_t)TILE_WORDS * 4u;
        #pragma unroll
        for (int i = 0; i < 8; i++) {
            int row = row_ld + i * 16;
            uint32_t off = (uint32_t)(row * PADK + kq_ld * 4) * 4u;
            CP_ASYNC16(a_s + off, Ab + (size_t)row * K + k0 + kq_ld * 4);
            CP_ASYNC16(b_s + off, Wb + (size_t)row * K + k0 + kq_ld * 4);
        }
    };

    float acc[4][8][4];
    #pragma unroll
    for (int i = 0; i < 4; i++)
        #pragma unroll
        for (int j = 0; j < 8; j++)
            #pragma unroll
            for (int r = 0; r < 4; r++) acc[i][j][r] = 0.f;

    issue_stage(0, 0); CP_COMMIT();
    if (NC > 1) issue_stage(1, 1);
    CP_COMMIT();

    for (int c = 0; c < NC; c++) {
        const int s = c % STAGES;
        CP_WAIT1();
        __syncthreads();
        if (c + 2 < NC) issue_stage(c + 2, (c + 2) % STAGES);
        CP_COMMIT();

        const uint32_t* a = sm + s * 2 * TILE_WORDS;
        const uint32_t* b = a + TILE_WORDS;

        #pragma unroll
        for (int kk = 0; kk < 4; kk++) {
            const int kb = kk * 8;
            uint32_t af[4][4], bf[8][2];
            #pragma unroll
            for (int i = 0; i < 4; i++) {
                const int row = wm * 64 + i * 16 + g;
                af[i][0] = a[row * PADK + kb + t];
                af[i][1] = a[(row + 8) * PADK + kb + t];
                af[i][2] = a[row * PADK + kb + t + 4];
                af[i][3] = a[(row + 8) * PADK + kb + t + 4];
            }
            #pragma unroll
            for (int j = 0; j < 8; j++) {
                const int col = wn * 64 + j * 8 + g;
                bf[j][0] = b[col * PADK + kb + t];
                bf[j][1] = b[col * PADK + kb + t + 4];
            }
            #pragma unroll
            for (int i = 0; i < 4; i++)
                #pragma unroll
                for (int j = 0; j < 8; j++) {
                    asm volatile(
                        "mma.sync.aligned.m16n8k8.row.col.f32.tf32.tf32.f32 "
                        "{%0, %1, %2, %3}, {%4, %5, %6, %7}, {%8, %9}, "
                        "{%0, %1, %2, %3};"
                        : "+f"(acc[i][j][0]), "+f"(acc[i][j][1]),
                          "+f"(acc[i][j][2]), "+f"(acc[i][j][3])
                        : "r"(af[i][0]), "r"(af[i][1]), "r"(af[i][2]), "r"(af[i][3]),
                          "r"(bf[j][0]), "r"(bf[j][1]));
                }
        }
        __syncthreads();
    }

    // ---- epilogue ----
    #pragma unroll
    for (int i = 0; i < 4; i++) {
        const int row = m0 + wm * 64 + i * 16 + g;
        #pragma unroll
        for (int j = 0; j < 8; j++) {
            const int col = n0 + wn * 64 + j * 8 + 2 * t;
            const float b0 = bias[col], b1 = bias[col + 1];
            float2 v0 = { acc[i][j][0] + b0, acc[i][j][1] + b1 };
            float2 v1 = { acc[i][j][2] + b0, acc[i][j][3] + b1 };
            if (RELU) {
                v0.x = rna_tf32(fmaxf(v0.x, 0.f)); v0.y = rna_tf32(fmaxf(v0.y, 0.f));
                v1.x = rna_tf32(fmaxf(v1.x, 0.f)); v1.y = rna_tf32(fmaxf(v1.y, 0.f));
            }
            *(float2*)(C + (size_t)row * N + col) = v0;
            *(float2*)(C + (size_t)(row + 8) * N + col) = v1;
        }
    }
}

// ---------------- value head: out[b] = tanh(enc[b,:] . Wv + bv) -------------
__global__ __launch_bounds__(256)
void vnet_kernel(const float* __restrict__ enc, const float* __restrict__ Wv,
                 const float* __restrict__ bv, float* __restrict__ out)
{
    __shared__ float red[8];
    const int b = blockIdx.x;
    float s = 0.f;
    for (int k = threadIdx.x; k < ENC_; k += 256)
        s = fmaf(enc[(size_t)b * ENC_ + k], Wv[k], s);
    #pragma unroll
    for (int o = 16; o > 0; o >>= 1) s += __shfl_down_sync(0xffffffff, s, o);
    if ((threadIdx.x & 31) == 0) red[threadIdx.x >> 5] = s;
    __syncthreads();
    if (threadIdx.x == 0) {
        float tot = 0.f;
        #pragma unroll
        for (int w = 0; w < 8; w++) tot += red[w];
        out[b] = tanhf(tot + bv[0]);
    }
}

// ---------------- GRU gate/mask update for step t ---------------------------
__device__ __forceinline__ float sigmoidf_(float x) { return 1.f / (1.f + expf(-x)); }

__global__ __launch_bounds__(256)
void gru_gate(const float* __restrict__ gi_all, const float* __restrict__ gh,
              const int* __restrict__ counts, float* __restrict__ h, int t)
{
    const int idx = blockIdx.x * 256 + threadIdx.x;  // over B*LAT
    const int b = idx / LAT_;
    const int j = idx - b * LAT_;
    const float* gib = gi_all + ((size_t)b * NMAX_ + t) * L3_;
    const float* ghb = gh + (size_t)b * L3_;
    float r = sigmoidf_(gib[j] + ghb[j]);
    float z = sigmoidf_(gib[LAT_ + j] + ghb[LAT_ + j]);
    float n = tanhf(gib[2 * LAT_ + j] + r * ghb[2 * LAT_ + j]);
    float hv = h[idx];
    float hn = (1.f - z) * n + z * hv;
    h[idx] = (t < counts[b]) ? rna_tf32(hn) : hv;
}

// ---------------- probs head: softmax(relu(h @ Wpr^T + bpr)) ----------------
__global__ __launch_bounds__(256)
void probs_kernel(const float* __restrict__ h, const float* __restrict__ Wpr,
                  const float* __restrict__ bpr, float* __restrict__ out)
{
    __shared__ float Ws[ACT_][LAT_];
    for (int i = threadIdx.x; i < ACT_ * LAT_; i += 256)
        Ws[i / LAT_][i % LAT_] = Wpr[i];
    __syncthreads();

    const int warp = threadIdx.x >> 5;
    const int lane = threadIdx.x & 31;
    const int b = blockIdx.x * 8 + warp;

    float a0 = 0.f, a1 = 0.f, a2 = 0.f;
    const float* hb = h + (size_t)b * LAT_;
    for (int k = lane; k < LAT_; k += 32) {
        float hv = hb[k];
        a0 = fmaf(hv, Ws[0][k], a0);
        a1 = fmaf(hv, Ws[1][k], a1);
        a2 = fmaf(hv, Ws[2][k], a2);
    }
    #pragma unroll
    for (int o = 16; o > 0; o >>= 1) {
        a0 += __shfl_down_sync(0xffffffff, a0, o);
        a1 += __shfl_down_sync(0xffffffff, a1, o);
        a2 += __shfl_down_sync(0xffffffff, a2, o);
    }
    if (lane == 0) {
        float l0 = fmaxf(a0 + bpr[0], 0.f);
        float l1 = fmaxf(a1 + bpr[1], 0.f);
        float l2 = fmaxf(a2 + bpr[2], 0.f);
        float m = fmaxf(l0, fmaxf(l1, l2));
        float e0 = expf(l0 - m), e1 = expf(l1 - m), e2 = expf(l2 - m);
        float inv = 1.f / (e0 + e1 + e2);
        out[(size_t)b * ACT_ + 0] = e0 * inv;
        out[(size_t)b * ACT_ + 1] = e1 * inv;
        out[(size_t)b * ACT_ + 2] = e2 * inv;
    }
}

// ---------------- launch ----------------------------------------------------
static inline void round_pass(const float* in, float* out, size_t n) {
    int n4 = (int)(n / 4);
    round_tf32_k<<<(n4 + 255) / 256, 256>>>(in, out, n4);
}

extern "C" void kernel_launch(void* const* d_in, const int* in_sizes, int n_in,
                              void* d_out, int out_size)
{
    const float* observation = (const float*)d_in[0];
    const float* neighbors   = (const float*)d_in[1];
    const int*   counts      = (const int*)  d_in[2];
    const float* W_ds  = (const float*)d_in[3];
    const float* b_ds  = (const float*)d_in[4];
    const float* W_pol = (const float*)d_in[5];
    const float* b_pol = (const float*)d_in[6];
    const float* W_v   = (const float*)d_in[7];
    const float* b_v   = (const float*)d_in[8];
    const float* W_ih  = (const float*)d_in[9];
    const float* b_ih  = (const float*)d_in[10];
    const float* W_hh  = (const float*)d_in[11];
    const float* b_hh  = (const float*)d_in[12];
    const float* W_pr  = (const float*)d_in[13];
    const float* b_pr  = (const float*)d_in[14];

    float* out_probs = (float*)d_out;                       // [B, 3]
    float* out_vals  = (float*)d_out + (size_t)B_ * ACT_;   // [B, 1]

    float *enc, *h, *gi, *gh, *obs_r, *nb_r, *Wds_r, *Wpol_r, *Wih_r, *Whh_r;
    cudaGetSymbolAddress((void**)&enc,   g_enc);
    cudaGetSymbolAddress((void**)&h,     g_h);
    cudaGetSymbolAddress((void**)&gi,    g_gi);
    cudaGetSymbolAddress((void**)&gh,    g_gh);
    cudaGetSymbolAddress((void**)&obs_r, g_obs_r);
    cudaGetSymbolAddress((void**)&nb_r,  g_nb_r);
    cudaGetSymbolAddress((void**)&Wds_r, g_Wds_r);
    cudaGetSymbolAddress((void**)&Wpol_r,g_Wpol_r);
    cudaGetSymbolAddress((void**)&Wih_r, g_Wih_r);
    cudaGetSymbolAddress((void**)&Whh_r, g_Whh_r);

    cudaFuncSetAttribute(gemm_mma<0>, cudaFuncAttributeMaxDynamicSharedMemorySize, SMEM_BYTES);
    cudaFuncSetAttribute(gemm_mma<1>, cudaFuncAttributeMaxDynamicSharedMemorySize, SMEM_BYTES);

    // 0) tf32-round all GEMM operands once
    round_pass(observation, obs_r, (size_t)B_ * OBS_);
    round_pass(neighbors,   nb_r,  (size_t)B_ * NMAX_ * LAT_);
    round_pass(W_ds,  Wds_r,  (size_t)ENC_ * OBS_);
    round_pass(W_pol, Wpol_r, (size_t)LAT_ * ENC_);
    round_pass(W_ih,  Wih_r,  (size_t)L3_ * LAT_);
    round_pass(W_hh,  Whh_r,  (size_t)L3_ * LAT_);

    // 1) enc = relu(obs @ W_ds^T + b_ds)   [4096 x 1024], K=4096
    gemm_mma<1><<<dim3(ENC_ / 128, B_ / 128), 128, SMEM_BYTES>>>(obs_r, Wds_r, b_ds, enc, ENC_, OBS_);

    // 2) h = relu(enc @ W_pol^T + b_pol)   [4096 x 512], K=1024
    gemm_mma<1><<<dim3(LAT_ / 128, B_ / 128), 128, SMEM_BYTES>>>(enc, Wpol_r, b_pol, h, LAT_, ENC_);

    // 3) state_vals = tanh(enc @ W_v^T + b_v)
    vnet_kernel<<<B_, 256>>>(enc, W_v, b_v, out_vals);

    // 4) gi (all 8 steps): [B*8, 1536] = neighbors[B*8,512] @ W_ih^T + b_ih
    gemm_mma<0><<<dim3(L3_ / 128, (B_ * NMAX_) / 128), 128, SMEM_BYTES>>>(nb_r, Wih_r, b_ih, gi, L3_, LAT_);

    // 5) sequential GRU
    for (int t = 0; t < NMAX_; t++) {
        gemm_mma<0><<<dim3(L3_ / 128, B_ / 128), 128, SMEM_BYTES>>>(h, Whh_r, b_hh, gh, L3_, LAT_);
        gru_gate<<<(B_ * LAT_) / 256, 256>>>(gi, gh, counts, h, t);
    }

    // 6) probs = softmax(relu(h @ W_pr^T + b_pr))
    probs_kernel<<<B_ / 8, 256>>>(h, W_pr, b_pr, out_probs);
}

// round 6
// speedup vs baseline: 5.5500x; 1.6195x over previous
#include <cuda_runtime.h>
#include <cuda_fp16.h>
#include <cstdint>
#include <math.h>

#define B_    4096
#define OBS_  4096
#define ENC_  1024
#define LAT_  512
#define L3_   1536   // 3*LAT
#define ACT_  3
#define NMAX_ 8

// ---------------- scratch (no allocations allowed) ----------------
__device__ __half g_enc[B_ * ENC_];           // fp16 activation
__device__ __half g_h  [B_ * LAT_];           // fp16 hidden state
__device__ float  g_gi [B_ * NMAX_ * L3_];    // fp32 (elementwise consumer)
__device__ float  g_gh [B_ * L3_];            // fp32
// fp16 copies of GEMM operands
__device__ __half g_obs_h [B_ * OBS_];
__device__ __half g_nb_h  [B_ * NMAX_ * LAT_];
__device__ __half g_Wds_h [ENC_ * OBS_];
__device__ __half g_Wpol_h[LAT_ * ENC_];
__device__ __half g_Wih_h [L3_ * LAT_];
__device__ __half g_Whh_h [L3_ * LAT_];

// ---------------- fp32 -> fp16 conversion pre-pass ----------------
__global__ __launch_bounds__(256)
void to_half_k(const float* __restrict__ in, __half* __restrict__ out, int n4)
{
    int i = blockIdx.x * 256 + threadIdx.x;
    if (i >= n4) return;
    float4 v = ((const float4*)in)[i];
    __half2 h0 = __floats2half2_rn(v.x, v.y);
    __half2 h1 = __floats2half2_rn(v.z, v.w);
    ((__half2*)out)[2 * i]     = h0;
    ((__half2*)out)[2 * i + 1] = h1;
}

// ====== fp16 mma.sync GEMM: C[M,N] = A[M,K]h @ W[N,K]h^T + bias(f32) =======
// CTA 128x128, 256 thr = 8 warps (2M x 4N), warp tile 64x32.
// K-chunk 64 halves (128B rows), 3-stage cp.async ring, ldmatrix fragments.
// Rows padded to 72 halves (144B) -> ldmatrix phases hit all 32 banks.
#define KCH   64
#define PADK  36                               // words per row (72 halves)
#define TILE_WORDS (128 * PADK)                // 18432 B per tile
#define STAGES 3
#define SMEM_BYTES (STAGES * 2 * TILE_WORDS * 4)   // 110592 B

#define CP_ASYNC16(dst, src) \
    asm volatile("cp.async.cg.shared.global [%0], [%1], 16;" :: "r"(dst), "l"(src))
#define CP_COMMIT()  asm volatile("cp.async.commit_group;" ::: "memory")
#define CP_WAIT1()   asm volatile("cp.async.wait_group 1;" ::: "memory")
#define LDSM_X4(r0, r1, r2, r3, addr) \
    asm volatile("ldmatrix.sync.aligned.m8n8.x4.shared.b16 {%0,%1,%2,%3}, [%4];" \
                 : "=r"(r0), "=r"(r1), "=r"(r2), "=r"(r3) : "r"(addr))

template<int RELU, int OUTH>   // OUTH=1: write __half output, else float
__global__ __launch_bounds__(256, 2)
void gemm_h(const __half* __restrict__ A, const __half* __restrict__ W,
            const float* __restrict__ bias, void* __restrict__ Cv,
            int N, int K)
{
    extern __shared__ uint32_t sm[];
    const uint32_t sbase = (uint32_t)__cvta_generic_to_shared(sm);

    const int tid  = threadIdx.x;
    const int wid  = tid >> 5;
    const int lane = tid & 31;
    const int g    = lane >> 2;
    const int t    = lane & 3;
    const int wm   = wid & 1;            // M half (64 rows)
    const int wn   = wid >> 1;           // N quarter (32 cols)

    const int n0 = blockIdx.x * 128;
    const int m0 = blockIdx.y * 128;
    const __half* Ab = A + (size_t)m0 * K;
    const __half* Wb = W + (size_t)n0 * K;
    const int NC = K / KCH;

    const int row_ld = tid >> 3;         // 0..31, advances by 32
    const int kq_ld  = tid & 7;          // 16B group within 128B row

    auto issue_stage = [&](int c, int s) {
        const int k0 = c * KCH;
        uint32_t a_st = sbase + (uint32_t)(s * 2 * TILE_WORDS) * 4u;
        uint32_t b_st = a_st + (uint32_t)TILE_WORDS * 4u;
        #pragma unroll
        for (int i = 0; i < 4; i++) {
            int row = row_ld + i * 32;
            uint32_t off = (uint32_t)(row * 144 + kq_ld * 16);
            CP_ASYNC16(a_st + off, Ab + (size_t)row * K + k0 + kq_ld * 8);
            CP_ASYNC16(b_st + off, Wb + (size_t)row * K + k0 + kq_ld * 8);
        }
    };

    float acc[4][4][4];
    #pragma unroll
    for (int i = 0; i < 4; i++)
        #pragma unroll
        for (int j = 0; j < 4; j++)
            #pragma unroll
            for (int r = 0; r < 4; r++) acc[i][j][r] = 0.f;

    issue_stage(0, 0); CP_COMMIT();
    if (NC > 1) issue_stage(1, 1);
    CP_COMMIT();

    // ldmatrix lane addressing (fixed per thread)
    const int lrow = lane & 15;          // row within 16-row tile pair
    const int lcol = (lane >> 4) * 16;   // 0 or 16 bytes (k 0-7 / 8-15)

    for (int c = 0; c < NC; c++) {
        const int s = c % STAGES;
        CP_WAIT1();
        __syncthreads();
        if (c + 2 < NC) issue_stage(c + 2, (c + 2) % STAGES);
        CP_COMMIT();

        const uint32_t a_st = sbase + (uint32_t)(s * 2 * TILE_WORDS) * 4u;
        const uint32_t b_st = a_st + (uint32_t)TILE_WORDS * 4u;

        #pragma unroll
        for (int kk = 0; kk < 4; kk++) {     // 4 k16 steps per 64-half chunk
            uint32_t af[4][4], bf[4][2];
            #pragma unroll
            for (int i = 0; i < 4; i++) {
                int row = wm * 64 + i * 16 + lrow;
                uint32_t addr = a_st + (uint32_t)(row * 144 + kk * 32 + lcol);
                LDSM_X4(af[i][0], af[i][1], af[i][2], af[i][3], addr);
            }
            #pragma unroll
            for (int j2 = 0; j2 < 2; j2++) {
                int row = wn * 32 + j2 * 16 + lrow;
                uint32_t addr = b_st + (uint32_t)(row * 144 + kk * 32 + lcol);
                uint32_t r0, r1, r2, r3;
                LDSM_X4(r0, r1, r2, r3, addr);
                bf[j2 * 2][0] = r0; bf[j2 * 2 + 1][0] = r1;
                bf[j2 * 2][1] = r2; bf[j2 * 2 + 1][1] = r3;
            }
            #pragma unroll
            for (int i = 0; i < 4; i++)
                #pragma unroll
                for (int j = 0; j < 4; j++) {
                    asm volatile(
                        "mma.sync.aligned.m16n8k16.row.col.f32.f16.f16.f32 "
                        "{%0, %1, %2, %3}, {%4, %5, %6, %7}, {%8, %9}, "
                        "{%0, %1, %2, %3};"
                        : "+f"(acc[i][j][0]), "+f"(acc[i][j][1]),
                          "+f"(acc[i][j][2]), "+f"(acc[i][j][3])
                        : "r"(af[i][0]), "r"(af[i][1]), "r"(af[i][2]), "r"(af[i][3]),
                          "r"(bf[j][0]), "r"(bf[j][1]));
                }
        }
        __syncthreads();
    }

    // ---- epilogue ----
    #pragma unroll
    for (int i = 0; i < 4; i++) {
        const int row = m0 + wm * 64 + i * 16 + g;
        #pragma unroll
        for (int j = 0; j < 4; j++) {
            const int col = n0 + wn * 32 + j * 8 + 2 * t;
            const float b0 = bias[col], b1 = bias[col + 1];
            float x0 = acc[i][j][0] + b0, x1 = acc[i][j][1] + b1;
            float x2 = acc[i][j][2] + b0, x3 = acc[i][j][3] + b1;
            if (RELU) {
                x0 = fmaxf(x0, 0.f); x1 = fmaxf(x1, 0.f);
                x2 = fmaxf(x2, 0.f); x3 = fmaxf(x3, 0.f);
            }
            if (OUTH) {
                __half* C = (__half*)Cv;
                *(__half2*)(C + (size_t)row * N + col)       = __floats2half2_rn(x0, x1);
                *(__half2*)(C + (size_t)(row + 8) * N + col) = __floats2half2_rn(x2, x3);
            } else {
                float* C = (float*)Cv;
                float2 v0 = {x0, x1}, v1 = {x2, x3};
                *(float2*)(C + (size_t)row * N + col)       = v0;
                *(float2*)(C + (size_t)(row + 8) * N + col) = v1;
            }
        }
    }
}

// ---------------- value head: out[b] = tanh(enc[b,:] . Wv + bv) -------------
__global__ __launch_bounds__(256)
void vnet_kernel(const __half* __restrict__ enc, const float* __restrict__ Wv,
                 const float* __restrict__ bv, float* __restrict__ out)
{
    __shared__ float red[8];
    const int b = blockIdx.x;
    float s = 0.f;
    for (int k = threadIdx.x; k < ENC_; k += 256)
        s = fmaf(__half2float(enc[(size_t)b * ENC_ + k]), Wv[k], s);
    #pragma unroll
    for (int o = 16; o > 0; o >>= 1) s += __shfl_down_sync(0xffffffff, s, o);
    if ((threadIdx.x & 31) == 0) red[threadIdx.x >> 5] = s;
    __syncthreads();
    if (threadIdx.x == 0) {
        float tot = 0.f;
        #pragma unroll
        for (int w = 0; w < 8; w++) tot += red[w];
        out[b] = tanhf(tot + bv[0]);
    }
}

// ---------------- GRU gate/mask update for step t ---------------------------
__device__ __forceinline__ float sigmoidf_(float x) { return 1.f / (1.f + expf(-x)); }

__global__ __launch_bounds__(256)
void gru_gate(const float* __restrict__ gi_all, const float* __restrict__ gh,
              const int* __restrict__ counts, __half* __restrict__ h, int t)
{
    const int idx = blockIdx.x * 256 + threadIdx.x;  // over B*LAT
    const int b = idx / LAT_;
    const int j = idx - b * LAT_;
    if (t >= counts[b]) return;
    const float* gib = gi_all + ((size_t)b * NMAX_ + t) * L3_;
    const float* ghb = gh + (size_t)b * L3_;
    float r = sigmoidf_(gib[j] + ghb[j]);
    float z = sigmoidf_(gib[LAT_ + j] + ghb[LAT_ + j]);
    float n = tanhf(gib[2 * LAT_ + j] + r * ghb[2 * LAT_ + j]);
    float hv = __half2float(h[idx]);
    h[idx] = __float2half_rn((1.f - z) * n + z * hv);
}

// ---------------- probs head: softmax(relu(h @ Wpr^T + bpr)) ----------------
__global__ __launch_bounds__(256)
void probs_kernel(const __half* __restrict__ h, const float* __restrict__ Wpr,
                  const float* __restrict__ bpr, float* __restrict__ out)
{
    __shared__ float Ws[ACT_][LAT_];
    for (int i = threadIdx.x; i < ACT_ * LAT_; i += 256)
        Ws[i / LAT_][i % LAT_] = Wpr[i];
    __syncthreads();

    const int warp = threadIdx.x >> 5;
    const int lane = threadIdx.x & 31;
    const int b = blockIdx.x * 8 + warp;

    float a0 = 0.f, a1 = 0.f, a2 = 0.f;
    const __half* hb = h + (size_t)b * LAT_;
    for (int k = lane; k < LAT_; k += 32) {
        float hv = __half2float(hb[k]);
        a0 = fmaf(hv, Ws[0][k], a0);
        a1 = fmaf(hv, Ws[1][k], a1);
        a2 = fmaf(hv, Ws[2][k], a2);
    }
    #pragma unroll
    for (int o = 16; o > 0; o >>= 1) {
        a0 += __shfl_down_sync(0xffffffff, a0, o);
        a1 += __shfl_down_sync(0xffffffff, a1, o);
        a2 += __shfl_down_sync(0xffffffff, a2, o);
    }
    if (lane == 0) {
        float l0 = fmaxf(a0 + bpr[0], 0.f);
        float l1 = fmaxf(a1 + bpr[1], 0.f);
        float l2 = fmaxf(a2 + bpr[2], 0.f);
        float m = fmaxf(l0, fmaxf(l1, l2));
        float e0 = expf(l0 - m), e1 = expf(l1 - m), e2 = expf(l2 - m);
        float inv = 1.f / (e0 + e1 + e2);
        out[(size_t)b * ACT_ + 0] = e0 * inv;
        out[(size_t)b * ACT_ + 1] = e1 * inv;
        out[(size_t)b * ACT_ + 2] = e2 * inv;
    }
}

// ---------------- launch ----------------------------------------------------
static inline void half_pass(const float* in, __half* out, size_t n) {
    int n4 = (int)(n / 4);
    to_half_k<<<(n4 + 255) / 256, 256>>>(in, out, n4);
}

extern "C" void kernel_launch(void* const* d_in, const int* in_sizes, int n_in,
                              void* d_out, int out_size)
{
    const float* observation = (const float*)d_in[0];
    const float* neighbors   = (const float*)d_in[1];
    const int*   counts      = (const int*)  d_in[2];
    const float* W_ds  = (const float*)d_in[3];
    const float* b_ds  = (const float*)d_in[4];
    const float* W_pol = (const float*)d_in[5];
    const float* b_pol = (const float*)d_in[6];
    const float* W_v   = (const float*)d_in[7];
    const float* b_v   = (const float*)d_in[8];
    const float* W_ih  = (const float*)d_in[9];
    const float* b_ih  = (const float*)d_in[10];
    const float* W_hh  = (const float*)d_in[11];
    const float* b_hh  = (const float*)d_in[12];
    const float* W_pr  = (const float*)d_in[13];
    const float* b_pr  = (const float*)d_in[14];

    float* out_probs = (float*)d_out;                       // [B, 3]
    float* out_vals  = (float*)d_out + (size_t)B_ * ACT_;   // [B, 1]

    __half *enc, *h, *obs_h, *nb_h, *Wds_h, *Wpol_h, *Wih_h, *Whh_h;
    float *gi, *gh;
    cudaGetSymbolAddress((void**)&enc,   g_enc);
    cudaGetSymbolAddress((void**)&h,     g_h);
    cudaGetSymbolAddress((void**)&gi,    g_gi);
    cudaGetSymbolAddress((void**)&gh,    g_gh);
    cudaGetSymbolAddress((void**)&obs_h, g_obs_h);
    cudaGetSymbolAddress((void**)&nb_h,  g_nb_h);
    cudaGetSymbolAddress((void**)&Wds_h, g_Wds_h);
    cudaGetSymbolAddress((void**)&Wpol_h,g_Wpol_h);
    cudaGetSymbolAddress((void**)&Wih_h, g_Wih_h);
    cudaGetSymbolAddress((void**)&Whh_h, g_Whh_h);

    cudaFuncSetAttribute(gemm_h<0,0>, cudaFuncAttributeMaxDynamicSharedMemorySize, SMEM_BYTES);
    cudaFuncSetAttribute(gemm_h<1,1>, cudaFuncAttributeMaxDynamicSharedMemorySize, SMEM_BYTES);

    // 0) fp16 conversion of all GEMM operands
    half_pass(observation, obs_h, (size_t)B_ * OBS_);
    half_pass(neighbors,   nb_h,  (size_t)B_ * NMAX_ * LAT_);
    half_pass(W_ds,  Wds_h,  (size_t)ENC_ * OBS_);
    half_pass(W_pol, Wpol_h, (size_t)LAT_ * ENC_);
    half_pass(W_ih,  Wih_h,  (size_t)L3_ * LAT_);
    half_pass(W_hh,  Whh_h,  (size_t)L3_ * LAT_);

    // 1) enc = relu(obs @ W_ds^T + b_ds)   [4096 x 1024], K=4096  (fp16 out)
    gemm_h<1,1><<<dim3(ENC_ / 128, B_ / 128), 256, SMEM_BYTES>>>(obs_h, Wds_h, b_ds, enc, ENC_, OBS_);

    // 2) h = relu(enc @ W_pol^T + b_pol)   [4096 x 512], K=1024   (fp16 out)
    gemm_h<1,1><<<dim3(LAT_ / 128, B_ / 128), 256, SMEM_BYTES>>>(enc, Wpol_h, b_pol, h, LAT_, ENC_);

    // 3) state_vals = tanh(enc @ W_v^T + b_v)
    vnet_kernel<<<B_, 256>>>(enc, W_v, b_v, out_vals);

    // 4) gi (all 8 steps): [B*8, 1536] = neighbors[B*8,512] @ W_ih^T + b_ih  (fp32 out)
    gemm_h<0,0><<<dim3(L3_ / 128, (B_ * NMAX_) / 128), 256, SMEM_BYTES>>>(nb_h, Wih_h, b_ih, gi, L3_, LAT_);

    // 5) sequential GRU
    for (int t = 0; t < NMAX_; t++) {
        gemm_h<0,0><<<dim3(L3_ / 128, B_ / 128), 256, SMEM_BYTES>>>(h, Whh_h, b_hh, gh, L3_, LAT_);
        gru_gate<<<(B_ * LAT_) / 256, 256>>>(gi, gh, counts, h, t);
    }

    // 6) probs = softmax(relu(h @ W_pr^T + b_pr))
    probs_kernel<<<B_ / 8, 256>>>(h, W_pr, b_pr, out_probs);
}

// round 7
// speedup vs baseline: 5.6954x; 1.0262x over previous
#include <cuda_runtime.h>
#include <cuda_fp16.h>
#include <cstdint>
#include <math.h>

#define B_    4096
#define OBS_  4096
#define ENC_  1024
#define LAT_  512
#define L3_   1536   // 3*LAT
#define ACT_  3
#define NMAX_ 8

// ---------------- scratch (no allocations allowed) ----------------
__device__ __half g_enc[B_ * ENC_];
__device__ __half g_h0 [B_ * LAT_];           // GRU hidden double buffer
__device__ __half g_h1 [B_ * LAT_];
__device__ float  g_gi [B_ * NMAX_ * L3_];    // compacted gi rows
__device__ __half g_obs_h [B_ * OBS_];
__device__ __half g_nb_c  [B_ * NMAX_ * LAT_]; // compacted fp16 neighbors
__device__ __half g_Wds_h [ENC_ * OBS_];
__device__ __half g_Wpol_h[LAT_ * ENC_];
__device__ __half g_Wih_h [L3_ * LAT_];
__device__ __half g_Whp   [L3_ * LAT_];       // gate-interleaved W_hh (fp16)
__device__ float  g_bhp   [L3_];              // gate-interleaved b_hh
__device__ int    g_offs  [B_];               // exclusive prefix of counts
__device__ int    g_Mc;                       // total valid rows

// ---------------- fp32 -> fp16 conversion pre-pass ----------------
__global__ __launch_bounds__(256)
void to_half_k(const float* __restrict__ in, __half* __restrict__ out, int n4)
{
    int i = blockIdx.x * 256 + threadIdx.x;
    if (i >= n4) return;
    float4 v = ((const float4*)in)[i];
    ((__half2*)out)[2 * i]     = __floats2half2_rn(v.x, v.y);
    ((__half2*)out)[2 * i + 1] = __floats2half2_rn(v.z, v.w);
}

// ---------------- prefix scan of counts (1 CTA) ----------------
__global__ __launch_bounds__(1024)
void scan_counts(const int* __restrict__ counts, int* __restrict__ offs,
                 int* __restrict__ Mc)
{
    __shared__ int ws[1024];
    const int tid = threadIdx.x;
    int c0 = counts[tid * 4], c1 = counts[tid * 4 + 1];
    int c2 = counts[tid * 4 + 2], c3 = counts[tid * 4 + 3];
    int s = c0 + c1 + c2 + c3;
    ws[tid] = s;
    __syncthreads();
    for (int o = 1; o < 1024; o <<= 1) {
        int v = (tid >= o) ? ws[tid - o] : 0;
        __syncthreads();
        ws[tid] += v;
        __syncthreads();
    }
    int ex = ws[tid] - s;
    offs[tid * 4]     = ex;
    offs[tid * 4 + 1] = ex + c0;
    offs[tid * 4 + 2] = ex + c0 + c1;
    offs[tid * 4 + 3] = ex + c0 + c1 + c2;
    if (tid == 1023) *Mc = ws[1023];
}

// ---------------- gather valid neighbor rows + fp16 convert ----------------
__global__ __launch_bounds__(256)
void gather_nb(const float* __restrict__ nb, const int* __restrict__ counts,
               const int* __restrict__ offs, __half* __restrict__ out)
{
    const int b = blockIdx.x;
    const int w = threadIdx.x >> 5;       // slot t
    const int lane = threadIdx.x & 31;
    if (w >= counts[b]) return;
    const float* src = nb + ((size_t)b * NMAX_ + w) * LAT_;
    __half* dst = out + (size_t)(offs[b] + w) * LAT_;
    #pragma unroll
    for (int it = 0; it < 4; it++) {
        float4 v = *(const float4*)(src + it * 128 + lane * 4);
        *(__half2*)(dst + it * 128 + lane * 4)     = __floats2half2_rn(v.x, v.y);
        *(__half2*)(dst + it * 128 + lane * 4 + 2) = __floats2half2_rn(v.z, v.w);
    }
}

// ---------------- permute W_hh/b_hh into gate-interleaved order -------------
// src row m = gate*512 + j  ->  dst row mp = ((j>>3)*3 + gate)*8 + (j&7)
__global__ __launch_bounds__(256)
void permute_whh(const float* __restrict__ Whh, const float* __restrict__ bhh,
                 __half* __restrict__ Whp, float* __restrict__ bhp)
{
    const int m = blockIdx.x * 8 + (threadIdx.x >> 5);
    const int lane = threadIdx.x & 31;
    const int gate = m >> 9, j = m & 511;
    const int mp = ((j >> 3) * 3 + gate) * 8 + (j & 7);
    const float* src = Whh + (size_t)m * LAT_;
    __half* dst = Whp + (size_t)mp * LAT_;
    #pragma unroll
    for (int it = 0; it < 4; it++) {
        float4 v = *(const float4*)(src + it * 128 + lane * 4);
        *(__half2*)(dst + it * 128 + lane * 4)     = __floats2half2_rn(v.x, v.y);
        *(__half2*)(dst + it * 128 + lane * 4 + 2) = __floats2half2_rn(v.z, v.w);
    }
    if (lane == 0) bhp[mp] = bhh[m];
}

// ====== fp16 mma.sync GEMM: C[M,N] = A[M,K]h @ W[N,K]h^T + bias(f32) =======
#define KCH   64
#define TILE_BYTES (128 * 144)
#define STAGES 3
#define SMEM_BYTES (STAGES * 2 * TILE_BYTES)   // 110592 B

#define CP_ASYNC16(dst, src) \
    asm volatile("cp.async.cg.shared.global [%0], [%1], 16;" :: "r"(dst), "l"(src))
#define CP_COMMIT()  asm volatile("cp.async.commit_group;" ::: "memory")
#define CP_WAIT1()   asm volatile("cp.async.wait_group 1;" ::: "memory")
#define LDSM_X4(r0, r1, r2, r3, addr) \
    asm volatile("ldmatrix.sync.aligned.m8n8.x4.shared.b16 {%0,%1,%2,%3}, [%4];" \
                 : "=r"(r0), "=r"(r1), "=r"(r2), "=r"(r3) : "r"(addr))
#define HMMA16(acc, a, b) \
    asm volatile("mma.sync.aligned.m16n8k16.row.col.f32.f16.f16.f32 " \
                 "{%0, %1, %2, %3}, {%4, %5, %6, %7}, {%8, %9}, {%0, %1, %2, %3};" \
                 : "+f"((acc)[0]), "+f"((acc)[1]), "+f"((acc)[2]), "+f"((acc)[3]) \
                 : "r"((a)[0]), "r"((a)[1]), "r"((a)[2]), "r"((a)[3]), \
                   "r"((b)[0]), "r"((b)[1]))

template<int RELU, int OUTH, int MCHK>
__global__ __launch_bounds__(256, 2)
void gemm_h(const __half* __restrict__ A, const __half* __restrict__ W,
            const float* __restrict__ bias, void* __restrict__ Cv,
            int N, int K, const int* __restrict__ mc)
{
    if (MCHK && (int)blockIdx.y * 128 >= *mc) return;
    extern __shared__ uint32_t sm[];
    const uint32_t sbase = (uint32_t)__cvta_generic_to_shared(sm);

    const int tid  = threadIdx.x;
    const int wid  = tid >> 5;
    const int lane = tid & 31;
    const int g    = lane >> 2;
    const int t    = lane & 3;
    const int wm   = wid & 1;
    const int wn   = wid >> 1;

    const int n0 = blockIdx.x * 128;
    const int m0 = blockIdx.y * 128;
    const __half* Ab = A + (size_t)m0 * K;
    const __half* Wb = W + (size_t)n0 * K;
    const int NC = K / KCH;

    const int row_ld = tid >> 3;
    const int kq_ld  = tid & 7;

    auto issue_stage = [&](int c, int s) {
        const int k0 = c * KCH;
        uint32_t a_st = sbase + (uint32_t)(s * 2 * TILE_BYTES);
        uint32_t b_st = a_st + (uint32_t)TILE_BYTES;
        #pragma unroll
        for (int i = 0; i < 4; i++) {
            int row = row_ld + i * 32;
            uint32_t off = (uint32_t)(row * 144 + kq_ld * 16);
            CP_ASYNC16(a_st + off, Ab + (size_t)row * K + k0 + kq_ld * 8);
            CP_ASYNC16(b_st + off, Wb + (size_t)row * K + k0 + kq_ld * 8);
        }
    };

    float acc[4][4][4];
    #pragma unroll
    for (int i = 0; i < 4; i++)
        #pragma unroll
        for (int j = 0; j < 4; j++)
            #pragma unroll
            for (int r = 0; r < 4; r++) acc[i][j][r] = 0.f;

    issue_stage(0, 0); CP_COMMIT();
    if (NC > 1) issue_stage(1, 1);
    CP_COMMIT();

    const int lrow = lane & 15;
    const int lcol = (lane >> 4) * 16;

    for (int c = 0; c < NC; c++) {
        const int s = c % STAGES;
        CP_WAIT1();
        __syncthreads();
        if (c + 2 < NC) issue_stage(c + 2, (c + 2) % STAGES);
        CP_COMMIT();

        const uint32_t a_st = sbase + (uint32_t)(s * 2 * TILE_BYTES);
        const uint32_t b_st = a_st + (uint32_t)TILE_BYTES;

        #pragma unroll
        for (int kk = 0; kk < 4; kk++) {
            uint32_t af[4][4], bf[4][2];
            #pragma unroll
            for (int i = 0; i < 4; i++) {
                int row = wm * 64 + i * 16 + lrow;
                LDSM_X4(af[i][0], af[i][1], af[i][2], af[i][3],
                        a_st + (uint32_t)(row * 144 + kk * 32 + lcol));
            }
            #pragma unroll
            for (int j2 = 0; j2 < 2; j2++) {
                int row = wn * 32 + j2 * 16 + lrow;
                uint32_t r0, r1, r2, r3;
                LDSM_X4(r0, r1, r2, r3, b_st + (uint32_t)(row * 144 + kk * 32 + lcol));
                bf[j2 * 2][0] = r0; bf[j2 * 2 + 1][0] = r1;
                bf[j2 * 2][1] = r2; bf[j2 * 2 + 1][1] = r3;
            }
            #pragma unroll
            for (int i = 0; i < 4; i++)
                #pragma unroll
                for (int j = 0; j < 4; j++)
                    HMMA16(acc[i][j], af[i], bf[j]);
        }
        __syncthreads();
    }

    #pragma unroll
    for (int i = 0; i < 4; i++) {
        const int row = m0 + wm * 64 + i * 16 + g;
        #pragma unroll
        for (int j = 0; j < 4; j++) {
            const int col = n0 + wn * 32 + j * 8 + 2 * t;
            const float b0 = bias[col], b1 = bias[col + 1];
            float x0 = acc[i][j][0] + b0, x1 = acc[i][j][1] + b1;
            float x2 = acc[i][j][2] + b0, x3 = acc[i][j][3] + b1;
            if (RELU) {
                x0 = fmaxf(x0, 0.f); x1 = fmaxf(x1, 0.f);
                x2 = fmaxf(x2, 0.f); x3 = fmaxf(x3, 0.f);
            }
            if (OUTH) {
                __half* C = (__half*)Cv;
                *(__half2*)(C + (size_t)row * N + col)       = __floats2half2_rn(x0, x1);
                *(__half2*)(C + (size_t)(row + 8) * N + col) = __floats2half2_rn(x2, x3);
            } else {
                float* C = (float*)Cv;
                float2 v0 = {x0, x1}, v1 = {x2, x3};
                *(float2*)(C + (size_t)row * N + col)       = v0;
                *(float2*)(C + (size_t)(row + 8) * N + col) = v1;
            }
        }
    }
}

// ====== fused GRU step: gh GEMM (gate-interleaved W) + gate + masked h ======
// CTA 128 rows x 192 interleaved cols (= 64 j's, 3 gates). grid (8, 32).
// 8 warps as 4M x 2N: warp tile 32 x 96 (12 n8 tiles = 4 j-groups x 3 gates).
#define GS_AT 18432                     // 128*144
#define GS_BT 27648                     // 192*144
#define GS_STAGE (GS_AT + GS_BT)
#define GS_SMEM (3 * GS_STAGE)          // 138240

__device__ __forceinline__ float sigmoidf_(float x) { return 1.f / (1.f + expf(-x)); }

__global__ __launch_bounds__(256, 1)
void gru_step(const __half* __restrict__ hin, const __half* __restrict__ Whp,
              const float* __restrict__ bhp, const float* __restrict__ gi,
              const int* __restrict__ counts, const int* __restrict__ offs,
              __half* __restrict__ hout, int tstep)
{
    extern __shared__ uint32_t sm[];
    const uint32_t sbase = (uint32_t)__cvta_generic_to_shared(sm);
    const int tid = threadIdx.x, wid = tid >> 5, lane = tid & 31;
    const int g = lane >> 2, t4 = lane & 3;
    const int wm = wid & 3;            // 4 M quadrants (32 rows)
    const int wn = wid >> 2;           // 2 N halves (96 cols)
    const int m0 = blockIdx.y * 128;
    const int bx = blockIdx.x;

    const __half* Ab = hin + (size_t)m0 * LAT_;
    const __half* Bb = Whp + (size_t)bx * 192 * LAT_;

    const int row_ld = tid >> 3;
    const int kq_ld  = tid & 7;

    auto issue = [&](int c, int s) {
        const int k0 = c * 64;
        uint32_t ast = sbase + (uint32_t)(s * GS_STAGE);
        uint32_t bst = ast + GS_AT;
        #pragma unroll
        for (int i = 0; i < 4; i++) {
            int row = row_ld + i * 32;
            CP_ASYNC16(ast + (uint32_t)(row * 144 + kq_ld * 16),
                       Ab + (size_t)row * LAT_ + k0 + kq_ld * 8);
        }
        #pragma unroll
        for (int i = 0; i < 6; i++) {
            int row = row_ld + i * 32;     // 0..191
            CP_ASYNC16(bst + (uint32_t)(row * 144 + kq_ld * 16),
                       Bb + (size_t)row * LAT_ + k0 + kq_ld * 8);
        }
    };

    float acc[2][12][4];
    #pragma unroll
    for (int i = 0; i < 2; i++)
        #pragma unroll
        for (int j = 0; j < 12; j++)
            #pragma unroll
            for (int r = 0; r < 4; r++) acc[i][j][r] = 0.f;

    issue(0, 0); CP_COMMIT();
    issue(1, 1); CP_COMMIT();

    const int lrow = lane & 15;
    const int lcol = (lane >> 4) * 16;

    for (int c = 0; c < 8; c++) {          // K = 512 = 8 chunks of 64
        const int s = c % 3;
        CP_WAIT1();
        __syncthreads();
        if (c + 2 < 8) issue(c + 2, (c + 2) % 3);
        CP_COMMIT();

        const uint32_t ast = sbase + (uint32_t)(s * GS_STAGE);
        const uint32_t bst = ast + GS_AT;

        #pragma unroll
        for (int kk = 0; kk < 4; kk++) {
            uint32_t af[2][4], bf[12][2];
            #pragma unroll
            for (int i = 0; i < 2; i++) {
                int row = wm * 32 + i * 16 + lrow;
                LDSM_X4(af[i][0], af[i][1], af[i][2], af[i][3],
                        ast + (uint32_t)(row * 144 + kk * 32 + lcol));
            }
            #pragma unroll
            for (int j2 = 0; j2 < 6; j2++) {
                int row = wn * 96 + j2 * 16 + lrow;
                uint32_t r0, r1, r2, r3;
                LDSM_X4(r0, r1, r2, r3, bst + (uint32_t)(row * 144 + kk * 32 + lcol));
                bf[j2 * 2][0] = r0; bf[j2 * 2 + 1][0] = r1;
                bf[j2 * 2][1] = r2; bf[j2 * 2 + 1][1] = r3;
            }
            #pragma unroll
            for (int i = 0; i < 2; i++)
                #pragma unroll
                for (int j = 0; j < 12; j++)
                    HMMA16(acc[i][j], af[i], bf[j]);
        }
        __syncthreads();
    }

    // ---- fused gate epilogue ----
    #pragma unroll
    for (int i = 0; i < 2; i++) {
        #pragma unroll
        for (int rh = 0; rh < 2; rh++) {
            const int row = m0 + wm * 32 + i * 16 + g + rh * 8;
            const int cnt = counts[row];
            const bool act = (tstep < cnt);
            const size_t girow = act ? (size_t)(offs[row] + tstep) * L3_ : 0;
            #pragma unroll
            for (int u = 0; u < 4; u++) {
                const int j0 = bx * 64 + (wn * 4 + u) * 8 + 2 * t4;
                const int cb = bx * 192 + wn * 96 + u * 24 + 2 * t4;
                const float ghr0 = acc[i][3*u  ][2*rh] + bhp[cb];
                const float ghr1 = acc[i][3*u  ][2*rh+1] + bhp[cb + 1];
                const float ghz0 = acc[i][3*u+1][2*rh] + bhp[cb + 8];
                const float ghz1 = acc[i][3*u+1][2*rh+1] + bhp[cb + 9];
                const float ghn0 = acc[i][3*u+2][2*rh] + bhp[cb + 16];
                const float ghn1 = acc[i][3*u+2][2*rh+1] + bhp[cb + 17];
                __half2 hold = *(const __half2*)(hin + (size_t)row * LAT_ + j0);
                float h0 = __low2float(hold), h1 = __high2float(hold);
                if (act) {
                    float2 gir = *(const float2*)(gi + girow + j0);
                    float2 giz = *(const float2*)(gi + girow + 512 + j0);
                    float2 gin = *(const float2*)(gi + girow + 1024 + j0);
                    float r0 = sigmoidf_(gir.x + ghr0);
                    float r1 = sigmoidf_(gir.y + ghr1);
                    float z0 = sigmoidf_(giz.x + ghz0);
                    float z1 = sigmoidf_(giz.y + ghz1);
                    float n0 = tanhf(gin.x + r0 * ghn0);
                    float n1 = tanhf(gin.y + r1 * ghn1);
                    h0 = (1.f - z0) * n0 + z0 * h0;
                    h1 = (1.f - z1) * n1 + z1 * h1;
                }
                *(__half2*)(hout + (size_t)row * LAT_ + j0) = __floats2half2_rn(h0, h1);
            }
        }
    }
}

// ---------------- value head ----------------
__global__ __launch_bounds__(256)
void vnet_kernel(const __half* __restrict__ enc, const float* __restrict__ Wv,
                 const float* __restrict__ bv, float* __restrict__ out)
{
    __shared__ float red[8];
    const int b = blockIdx.x;
    float s = 0.f;
    for (int k = threadIdx.x; k < ENC_; k += 256)
        s = fmaf(__half2float(enc[(size_t)b * ENC_ + k]), Wv[k], s);
    #pragma unroll
    for (int o = 16; o > 0; o >>= 1) s += __shfl_down_sync(0xffffffff, s, o);
    if ((threadIdx.x & 31) == 0) red[threadIdx.x >> 5] = s;
    __syncthreads();
    if (threadIdx.x == 0) {
        float tot = 0.f;
        #pragma unroll
        for (int w = 0; w < 8; w++) tot += red[w];
        out[b] = tanhf(tot + bv[0]);
    }
}

// ---------------- probs head ----------------
__global__ __launch_bounds__(256)
void probs_kernel(const __half* __restrict__ h, const float* __restrict__ Wpr,
                  const float* __restrict__ bpr, float* __restrict__ out)
{
    __shared__ float Ws[ACT_][LAT_];
    for (int i = threadIdx.x; i < ACT_ * LAT_; i += 256)
        Ws[i / LAT_][i % LAT_] = Wpr[i];
    __syncthreads();

    const int warp = threadIdx.x >> 5;
    const int lane = threadIdx.x & 31;
    const int b = blockIdx.x * 8 + warp;

    float a0 = 0.f, a1 = 0.f, a2 = 0.f;
    const __half* hb = h + (size_t)b * LAT_;
    for (int k = lane; k < LAT_; k += 32) {
        float hv = __half2float(hb[k]);
        a0 = fmaf(hv, Ws[0][k], a0);
        a1 = fmaf(hv, Ws[1][k], a1);
        a2 = fmaf(hv, Ws[2][k], a2);
    }
    #pragma unroll
    for (int o = 16; o > 0; o >>= 1) {
        a0 += __shfl_down_sync(0xffffffff, a0, o);
        a1 += __shfl_down_sync(0xffffffff, a1, o);
        a2 += __shfl_down_sync(0xffffffff, a2, o);
    }
    if (lane == 0) {
        float l0 = fmaxf(a0 + bpr[0], 0.f);
        float l1 = fmaxf(a1 + bpr[1], 0.f);
        float l2 = fmaxf(a2 + bpr[2], 0.f);
        float m = fmaxf(l0, fmaxf(l1, l2));
        float e0 = expf(l0 - m), e1 = expf(l1 - m), e2 = expf(l2 - m);
        float inv = 1.f / (e0 + e1 + e2);
        out[(size_t)b * ACT_ + 0] = e0 * inv;
        out[(size_t)b * ACT_ + 1] = e1 * inv;
        out[(size_t)b * ACT_ + 2] = e2 * inv;
    }
}

// ---------------- launch ----------------
static inline void half_pass(const float* in, __half* out, size_t n) {
    int n4 = (int)(n / 4);
    to_half_k<<<(n4 + 255) / 256, 256>>>(in, out, n4);
}

extern "C" void kernel_launch(void* const* d_in, const int* in_sizes, int n_in,
                              void* d_out, int out_size)
{
    const float* observation = (const float*)d_in[0];
    const float* neighbors   = (const float*)d_in[1];
    const int*   counts      = (const int*)  d_in[2];
    const float* W_ds  = (const float*)d_in[3];
    const float* b_ds  = (const float*)d_in[4];
    const float* W_pol = (const float*)d_in[5];
    const float* b_pol = (const float*)d_in[6];
    const float* W_v   = (const float*)d_in[7];
    const float* b_v   = (const float*)d_in[8];
    const float* W_ih  = (const float*)d_in[9];
    const float* b_ih  = (const float*)d_in[10];
    const float* W_hh  = (const float*)d_in[11];
    const float* b_hh  = (const float*)d_in[12];
    const float* W_pr  = (const float*)d_in[13];
    const float* b_pr  = (const float*)d_in[14];

    float* out_probs = (float*)d_out;
    float* out_vals  = (float*)d_out + (size_t)B_ * ACT_;

    __half *enc, *h0, *h1, *obs_h, *nb_c, *Wds_h, *Wpol_h, *Wih_h, *Whp;
    float *gi, *bhp;
    int *offs, *Mc;
    cudaGetSymbolAddress((void**)&enc,   g_enc);
    cudaGetSymbolAddress((void**)&h0,    g_h0);
    cudaGetSymbolAddress((void**)&h1,    g_h1);
    cudaGetSymbolAddress((void**)&gi,    g_gi);
    cudaGetSymbolAddress((void**)&obs_h, g_obs_h);
    cudaGetSymbolAddress((void**)&nb_c,  g_nb_c);
    cudaGetSymbolAddress((void**)&Wds_h, g_Wds_h);
    cudaGetSymbolAddress((void**)&Wpol_h,g_Wpol_h);
    cudaGetSymbolAddress((void**)&Wih_h, g_Wih_h);
    cudaGetSymbolAddress((void**)&Whp,   g_Whp);
    cudaGetSymbolAddress((void**)&bhp,   g_bhp);
    cudaGetSymbolAddress((void**)&offs,  g_offs);
    cudaGetSymbolAddress((void**)&Mc,    g_Mc);

    cudaFuncSetAttribute(gemm_h<0,0,1>, cudaFuncAttributeMaxDynamicSharedMemorySize, SMEM_BYTES);
    cudaFuncSetAttribute(gemm_h<1,1,0>, cudaFuncAttributeMaxDynamicSharedMemorySize, SMEM_BYTES);
    cudaFuncSetAttribute(gru_step, cudaFuncAttributeMaxDynamicSharedMemorySize, GS_SMEM);

    // 0) prep: scan + gather + conversions + W_hh permute
    scan_counts<<<1, 1024>>>(counts, offs, Mc);
    gather_nb<<<B_, 256>>>(neighbors, counts, offs, nb_c);
    half_pass(observation, obs_h, (size_t)B_ * OBS_);
    half_pass(W_ds,  Wds_h,  (size_t)ENC_ * OBS_);
    half_pass(W_pol, Wpol_h, (size_t)LAT_ * ENC_);
    half_pass(W_ih,  Wih_h,  (size_t)L3_ * LAT_);
    permute_whh<<<L3_ / 8, 256>>>(W_hh, b_hh, Whp, bhp);

    // 1) enc = relu(obs @ W_ds^T + b_ds)
    gemm_h<1,1,0><<<dim3(ENC_ / 128, B_ / 128), 256, SMEM_BYTES>>>(obs_h, Wds_h, b_ds, enc, ENC_, OBS_, nullptr);

    // 2) h0 = relu(enc @ W_pol^T + b_pol)
    gemm_h<1,1,0><<<dim3(LAT_ / 128, B_ / 128), 256, SMEM_BYTES>>>(enc, Wpol_h, b_pol, h0, LAT_, ENC_, nullptr);

    // 3) state_vals
    vnet_kernel<<<B_, 256>>>(enc, W_v, b_v, out_vals);

    // 4) gi over compacted rows (early-exit past Mc)
    gemm_h<0,0,1><<<dim3(L3_ / 128, (B_ * NMAX_) / 128), 256, SMEM_BYTES>>>(nb_c, Wih_h, b_ih, gi, L3_, LAT_, Mc);

    // 5) fused GRU steps (double-buffered h)
    for (int t = 0; t < NMAX_; t++) {
        const __half* hi = (t & 1) ? h1 : h0;
        __half* ho       = (t & 1) ? h0 : h1;
        gru_step<<<dim3(8, 32), 256, GS_SMEM>>>(hi, Whp, bhp, gi, counts, offs, ho, t);
    }

    // 6) probs (final h in h0 after 8 steps)
    probs_kernel<<<B_ / 8, 256>>>(h0, W_pr, b_pr, out_probs);
}

// round 8
// speedup vs baseline: 6.5428x; 1.1488x over previous
#include <cuda_runtime.h>
#include <cuda_fp16.h>
#include <cstdint>
#include <math.h>

#define B_    4096
#define OBS_  4096
#define ENC_  1024
#define LAT_  512
#define L3_   1536
#define ACT_  3
#define NMAX_ 8

// ---------------- scratch ----------------
__device__ __half g_enc[B_ * ENC_];
__device__ __half g_h0 [B_ * LAT_];           // sorted-space hidden, dbl buffer
__device__ __half g_h1 [B_ * LAT_];
__device__ float  g_gi [B_ * NMAX_ * L3_];    // compacted gi rows (orig-space)
__device__ __half g_obs_h [B_ * OBS_];
__device__ __half g_nb_c  [B_ * NMAX_ * LAT_];
__device__ __half g_Wds_h [ENC_ * OBS_];
__device__ __half g_Wpol_h[LAT_ * ENC_];
__device__ __half g_Wih_h [L3_ * LAT_];
__device__ __half g_Whp   [L3_ * LAT_];
__device__ float  g_bhp   [L3_];
__device__ int    g_offs  [B_];               // exclusive prefix of counts
__device__ int    g_Mc;
__device__ int    g_perm  [B_];               // orig -> sorted
__device__ int    g_order [B_];               // sorted -> orig
__device__ int    g_cnt_s [B_];               // counts in sorted order
__device__ int    g_base_s[B_];               // offs in sorted order
__device__ int    g_active[NMAX_];            // #rows active at step t

// ---------------- fp32 -> fp16 conversion ----------------
__global__ __launch_bounds__(256)
void to_half_k(const float* __restrict__ in, __half* __restrict__ out, int n4)
{
    int i = blockIdx.x * 256 + threadIdx.x;
    if (i >= n4) return;
    float4 v = ((const float4*)in)[i];
    ((__half2*)out)[2 * i]     = __floats2half2_rn(v.x, v.y);
    ((__half2*)out)[2 * i + 1] = __floats2half2_rn(v.z, v.w);
}

// ---------------- prefix scan of counts (1 CTA) ----------------
__global__ __launch_bounds__(1024)
void scan_counts(const int* __restrict__ counts, int* __restrict__ offs,
                 int* __restrict__ Mc)
{
    __shared__ int ws[1024];
    const int tid = threadIdx.x;
    int c0 = counts[tid * 4], c1 = counts[tid * 4 + 1];
    int c2 = counts[tid * 4 + 2], c3 = counts[tid * 4 + 3];
    int s = c0 + c1 + c2 + c3;
    ws[tid] = s;
    __syncthreads();
    for (int o = 1; o < 1024; o <<= 1) {
        int v = (tid >= o) ? ws[tid - o] : 0;
        __syncthreads();
        ws[tid] += v;
        __syncthreads();
    }
    int ex = ws[tid] - s;
    offs[tid * 4]     = ex;
    offs[tid * 4 + 1] = ex + c0;
    offs[tid * 4 + 2] = ex + c0 + c1;
    offs[tid * 4 + 3] = ex + c0 + c1 + c2;
    if (tid == 1023) *Mc = ws[1023];
}

// -------- deterministic counting sort by count, descending (1 CTA) ---------
__global__ __launch_bounds__(1024)
void sort_counts(const int* __restrict__ counts, int* __restrict__ perm,
                 int* __restrict__ order, int* __restrict__ active)
{
    __shared__ int hist[9][1024];
    const int tid = threadIdx.x;
    int c[4];
    #pragma unroll
    for (int i = 0; i < 4; i++) c[i] = counts[tid * 4 + i];
    int loc[9];
    #pragma unroll
    for (int b = 0; b < 9; b++) loc[b] = 0;
    #pragma unroll
    for (int i = 0; i < 4; i++) loc[c[i]]++;
    #pragma unroll
    for (int b = 0; b < 9; b++) hist[b][tid] = loc[b];
    __syncthreads();
    for (int o = 1; o < 1024; o <<= 1) {
        int v[9];
        #pragma unroll
        for (int b = 0; b < 9; b++) v[b] = (tid >= o) ? hist[b][tid - o] : 0;
        __syncthreads();
        #pragma unroll
        for (int b = 0; b < 9; b++) hist[b][tid] += v[b];
        __syncthreads();
    }
    int total[9], start[9];
    #pragma unroll
    for (int b = 0; b < 9; b++) total[b] = hist[b][1023];
    int a = 0;
    for (int b = 8; b >= 0; b--) { start[b] = a; a += total[b]; }
    int ex[9];
    #pragma unroll
    for (int b = 0; b < 9; b++) ex[b] = hist[b][tid] - loc[b];
    #pragma unroll
    for (int i = 0; i < 4; i++) {
        int b = tid * 4 + i, cc = c[i];
        int pos = start[cc] + ex[cc]++;
        perm[b] = pos;
        order[pos] = b;
    }
    if (tid < NMAX_) active[tid] = start[tid];   // #rows with count > t
}

__global__ __launch_bounds__(256)
void fill_sorted(const int* __restrict__ order, const int* __restrict__ counts,
                 const int* __restrict__ offs, int* __restrict__ cnt_s,
                 int* __restrict__ base_s)
{
    int p = blockIdx.x * 256 + threadIdx.x;
    int b = order[p];
    cnt_s[p] = counts[b];
    base_s[p] = offs[b];
}

// ---------------- gather valid neighbor rows + fp16 convert ----------------
__global__ __launch_bounds__(256)
void gather_nb(const float* __restrict__ nb, const int* __restrict__ counts,
               const int* __restrict__ offs, __half* __restrict__ out)
{
    const int b = blockIdx.x;
    const int w = threadIdx.x >> 5;
    const int lane = threadIdx.x & 31;
    if (w >= counts[b]) return;
    const float* src = nb + ((size_t)b * NMAX_ + w) * LAT_;
    __half* dst = out + (size_t)(offs[b] + w) * LAT_;
    #pragma unroll
    for (int it = 0; it < 4; it++) {
        float4 v = *(const float4*)(src + it * 128 + lane * 4);
        *(__half2*)(dst + it * 128 + lane * 4)     = __floats2half2_rn(v.x, v.y);
        *(__half2*)(dst + it * 128 + lane * 4 + 2) = __floats2half2_rn(v.z, v.w);
    }
}

// ---------------- permute W_hh/b_hh gate-interleaved -------------
__global__ __launch_bounds__(256)
void permute_whh(const float* __restrict__ Whh, const float* __restrict__ bhh,
                 __half* __restrict__ Whp, float* __restrict__ bhp)
{
    const int m = blockIdx.x * 8 + (threadIdx.x >> 5);
    const int lane = threadIdx.x & 31;
    const int gate = m >> 9, j = m & 511;
    const int mp = ((j >> 3) * 3 + gate) * 8 + (j & 7);
    const float* src = Whh + (size_t)m * LAT_;
    __half* dst = Whp + (size_t)mp * LAT_;
    #pragma unroll
    for (int it = 0; it < 4; it++) {
        float4 v = *(const float4*)(src + it * 128 + lane * 4);
        *(__half2*)(dst + it * 128 + lane * 4)     = __floats2half2_rn(v.x, v.y);
        *(__half2*)(dst + it * 128 + lane * 4 + 2) = __floats2half2_rn(v.z, v.w);
    }
    if (lane == 0) bhp[mp] = bhh[m];
}

// ====== fp16 mma.sync GEMM ======
#define KCH   64
#define TILE_BYTES (128 * 144)
#define STAGES 3
#define SMEM_BYTES (STAGES * 2 * TILE_BYTES)

#define CP_ASYNC16(dst, src) \
    asm volatile("cp.async.cg.shared.global [%0], [%1], 16;" :: "r"(dst), "l"(src))
#define CP_COMMIT()  asm volatile("cp.async.commit_group;" ::: "memory")
#define CP_WAIT1()   asm volatile("cp.async.wait_group 1;" ::: "memory")
#define LDSM_X4(r0, r1, r2, r3, addr) \
    asm volatile("ldmatrix.sync.aligned.m8n8.x4.shared.b16 {%0,%1,%2,%3}, [%4];" \
                 : "=r"(r0), "=r"(r1), "=r"(r2), "=r"(r3) : "r"(addr))
#define HMMA16(acc, a, b) \
    asm volatile("mma.sync.aligned.m16n8k16.row.col.f32.f16.f16.f32 " \
                 "{%0, %1, %2, %3}, {%4, %5, %6, %7}, {%8, %9}, {%0, %1, %2, %3};" \
                 : "+f"((acc)[0]), "+f"((acc)[1]), "+f"((acc)[2]), "+f"((acc)[3]) \
                 : "r"((a)[0]), "r"((a)[1]), "r"((a)[2]), "r"((a)[3]), \
                   "r"((b)[0]), "r"((b)[1]))

template<int RELU, int OUTH, int MCHK, int PERM>
__global__ __launch_bounds__(256, 2)
void gemm_h(const __half* __restrict__ A, const __half* __restrict__ W,
            const float* __restrict__ bias, void* __restrict__ Cv,
            int N, int K, const int* __restrict__ mc, const int* __restrict__ perm)
{
    if (MCHK && (int)blockIdx.y * 128 >= *mc) return;
    extern __shared__ uint32_t sm[];
    const uint32_t sbase = (uint32_t)__cvta_generic_to_shared(sm);

    const int tid  = threadIdx.x;
    const int wid  = tid >> 5;
    const int lane = tid & 31;
    const int g    = lane >> 2;
    const int t    = lane & 3;
    const int wm   = wid & 1;
    const int wn   = wid >> 1;

    const int n0 = blockIdx.x * 128;
    const int m0 = blockIdx.y * 128;
    const __half* Ab = A + (size_t)m0 * K;
    const __half* Wb = W + (size_t)n0 * K;
    const int NC = K / KCH;

    const int row_ld = tid >> 3;
    const int kq_ld  = tid & 7;

    auto issue_stage = [&](int c, int s) {
        const int k0 = c * KCH;
        uint32_t a_st = sbase + (uint32_t)(s * 2 * TILE_BYTES);
        uint32_t b_st = a_st + (uint32_t)TILE_BYTES;
        #pragma unroll
        for (int i = 0; i < 4; i++) {
            int row = row_ld + i * 32;
            uint32_t off = (uint32_t)(row * 144 + kq_ld * 16);
            CP_ASYNC16(a_st + off, Ab + (size_t)row * K + k0 + kq_ld * 8);
            CP_ASYNC16(b_st + off, Wb + (size_t)row * K + k0 + kq_ld * 8);
        }
    };

    float acc[4][4][4];
    #pragma unroll
    for (int i = 0; i < 4; i++)
        #pragma unroll
        for (int j = 0; j < 4; j++)
            #pragma unroll
            for (int r = 0; r < 4; r++) acc[i][j][r] = 0.f;

    issue_stage(0, 0); CP_COMMIT();
    if (NC > 1) issue_stage(1, 1);
    CP_COMMIT();

    const int lrow = lane & 15;
    const int lcol = (lane >> 4) * 16;

    for (int c = 0; c < NC; c++) {
        const int s = c % STAGES;
        CP_WAIT1();
        __syncthreads();
        if (c + 2 < NC) issue_stage(c + 2, (c + 2) % STAGES);
        CP_COMMIT();

        const uint32_t a_st = sbase + (uint32_t)(s * 2 * TILE_BYTES);
        const uint32_t b_st = a_st + (uint32_t)TILE_BYTES;

        #pragma unroll
        for (int kk = 0; kk < 4; kk++) {
            uint32_t af[4][4], bf[4][2];
            #pragma unroll
            for (int i = 0; i < 4; i++) {
                int row = wm * 64 + i * 16 + lrow;
                LDSM_X4(af[i][0], af[i][1], af[i][2], af[i][3],
                        a_st + (uint32_t)(row * 144 + kk * 32 + lcol));
            }
            #pragma unroll
            for (int j2 = 0; j2 < 2; j2++) {
                int row = wn * 32 + j2 * 16 + lrow;
                uint32_t r0, r1, r2, r3;
                LDSM_X4(r0, r1, r2, r3, b_st + (uint32_t)(row * 144 + kk * 32 + lcol));
                bf[j2 * 2][0] = r0; bf[j2 * 2 + 1][0] = r1;
                bf[j2 * 2][1] = r2; bf[j2 * 2 + 1][1] = r3;
            }
            #pragma unroll
            for (int i = 0; i < 4; i++)
                #pragma unroll
                for (int j = 0; j < 4; j++)
                    HMMA16(acc[i][j], af[i], bf[j]);
        }
        __syncthreads();
    }

    #pragma unroll
    for (int i = 0; i < 4; i++) {
        const int row = m0 + wm * 64 + i * 16 + g;
        const int orow0 = PERM ? perm[row] : row;
        const int orow1 = PERM ? perm[row + 8] : row + 8;
        #pragma unroll
        for (int j = 0; j < 4; j++) {
            const int col = n0 + wn * 32 + j * 8 + 2 * t;
            const float b0 = bias[col], b1 = bias[col + 1];
            float x0 = acc[i][j][0] + b0, x1 = acc[i][j][1] + b1;
            float x2 = acc[i][j][2] + b0, x3 = acc[i][j][3] + b1;
            if (RELU) {
                x0 = fmaxf(x0, 0.f); x1 = fmaxf(x1, 0.f);
                x2 = fmaxf(x2, 0.f); x3 = fmaxf(x3, 0.f);
            }
            if (OUTH) {
                __half* C = (__half*)Cv;
                *(__half2*)(C + (size_t)orow0 * N + col) = __floats2half2_rn(x0, x1);
                *(__half2*)(C + (size_t)orow1 * N + col) = __floats2half2_rn(x2, x3);
            } else {
                float* C = (float*)Cv;
                float2 v0 = {x0, x1}, v1 = {x2, x3};
                *(float2*)(C + (size_t)orow0 * N + col) = v0;
                *(float2*)(C + (size_t)orow1 * N + col) = v1;
            }
        }
    }
}

// ====== fused GRU step (sorted rows; inactive tail CTAs just copy) ======
#define GS_AT 18432
#define GS_BT 27648
#define GS_STAGE (GS_AT + GS_BT)
#define GS_SMEM (3 * GS_STAGE)

__device__ __forceinline__ float sigmoidf_(float x) { return 1.f / (1.f + expf(-x)); }

__global__ __launch_bounds__(256, 1)
void gru_step(const __half* __restrict__ hin, const __half* __restrict__ Whp,
              const float* __restrict__ bhp, const float* __restrict__ gi,
              const int* __restrict__ cnt_s, const int* __restrict__ base_s,
              const int* __restrict__ active, __half* __restrict__ hout, int tstep)
{
    const int m0 = blockIdx.y * 128;
    const int bx = blockIdx.x;
    const int tid = threadIdx.x;
    const int nact = active[tstep];

    if (m0 >= nact) {
        // pure copy of this CTA's h slice: rows m0..m0+127, j cols bx*64..+63
        for (int idx = tid; idx < 128 * 32; idx += 256) {
            int row = m0 + (idx >> 5);
            int c2 = idx & 31;
            *(__half2*)(hout + (size_t)row * LAT_ + bx * 64 + c2 * 2) =
                *(const __half2*)(hin + (size_t)row * LAT_ + bx * 64 + c2 * 2);
        }
        return;
    }

    extern __shared__ uint32_t sm[];
    const uint32_t sbase = (uint32_t)__cvta_generic_to_shared(sm);
    const int wid = tid >> 5, lane = tid & 31;
    const int g = lane >> 2, t4 = lane & 3;
    const int wm = wid & 3;
    const int wn = wid >> 2;

    const __half* Ab = hin + (size_t)m0 * LAT_;
    const __half* Bb = Whp + (size_t)bx * 192 * LAT_;

    const int row_ld = tid >> 3;
    const int kq_ld  = tid & 7;

    auto issue = [&](int c, int s) {
        const int k0 = c * 64;
        uint32_t ast = sbase + (uint32_t)(s * GS_STAGE);
        uint32_t bst = ast + GS_AT;
        #pragma unroll
        for (int i = 0; i < 4; i++) {
            int row = row_ld + i * 32;
            CP_ASYNC16(ast + (uint32_t)(row * 144 + kq_ld * 16),
                       Ab + (size_t)row * LAT_ + k0 + kq_ld * 8);
        }
        #pragma unroll
        for (int i = 0; i < 6; i++) {
            int row = row_ld + i * 32;
            CP_ASYNC16(bst + (uint32_t)(row * 144 + kq_ld * 16),
                       Bb + (size_t)row * LAT_ + k0 + kq_ld * 8);
        }
    };

    float acc[2][12][4];
    #pragma unroll
    for (int i = 0; i < 2; i++)
        #pragma unroll
        for (int j = 0; j < 12; j++)
            #pragma unroll
            for (int r = 0; r < 4; r++) acc[i][j][r] = 0.f;

    issue(0, 0); CP_COMMIT();
    issue(1, 1); CP_COMMIT();

    const int lrow = lane & 15;
    const int lcol = (lane >> 4) * 16;

    for (int c = 0; c < 8; c++) {
        const int s = c % 3;
        CP_WAIT1();
        __syncthreads();
        if (c + 2 < 8) issue(c + 2, (c + 2) % 3);
        CP_COMMIT();

        const uint32_t ast = sbase + (uint32_t)(s * GS_STAGE);
        const uint32_t bst = ast + GS_AT;

        #pragma unroll
        for (int kk = 0; kk < 4; kk++) {
            uint32_t af[2][4], bf[12][2];
            #pragma unroll
            for (int i = 0; i < 2; i++) {
                int row = wm * 32 + i * 16 + lrow;
                LDSM_X4(af[i][0], af[i][1], af[i][2], af[i][3],
                        ast + (uint32_t)(row * 144 + kk * 32 + lcol));
            }
            #pragma unroll
            for (int j2 = 0; j2 < 6; j2++) {
                int row = wn * 96 + j2 * 16 + lrow;
                uint32_t r0, r1, r2, r3;
                LDSM_X4(r0, r1, r2, r3, bst + (uint32_t)(row * 144 + kk * 32 + lcol));
                bf[j2 * 2][0] = r0; bf[j2 * 2 + 1][0] = r1;
                bf[j2 * 2][1] = r2; bf[j2 * 2 + 1][1] = r3;
            }
            #pragma unroll
            for (int i = 0; i < 2; i++)
                #pragma unroll
                for (int j = 0; j < 12; j++)
                    HMMA16(acc[i][j], af[i], bf[j]);
        }
        __syncthreads();
    }

    #pragma unroll
    for (int i = 0; i < 2; i++) {
        #pragma unroll
        for (int rh = 0; rh < 2; rh++) {
            const int row = m0 + wm * 32 + i * 16 + g + rh * 8;
            const bool act = (tstep < cnt_s[row]);
            const size_t girow = act ? (size_t)(base_s[row] + tstep) * L3_ : 0;
            #pragma unroll
            for (int u = 0; u < 4; u++) {
                const int j0 = bx * 64 + (wn * 4 + u) * 8 + 2 * t4;
                const int cb = bx * 192 + wn * 96 + u * 24 + 2 * t4;
                const float ghr0 = acc[i][3*u  ][2*rh]   + bhp[cb];
                const float ghr1 = acc[i][3*u  ][2*rh+1] + bhp[cb + 1];
                const float ghz0 = acc[i][3*u+1][2*rh]   + bhp[cb + 8];
                const float ghz1 = acc[i][3*u+1][2*rh+1] + bhp[cb + 9];
                const float ghn0 = acc[i][3*u+2][2*rh]   + bhp[cb + 16];
                const float ghn1 = acc[i][3*u+2][2*rh+1] + bhp[cb + 17];
                __half2 hold = *(const __half2*)(hin + (size_t)row * LAT_ + j0);
                float h0 = __low2float(hold), h1 = __high2float(hold);
                if (act) {
                    float2 gir = *(const float2*)(gi + girow + j0);
                    float2 giz = *(const float2*)(gi + girow + 512 + j0);
                    float2 gin = *(const float2*)(gi + girow + 1024 + j0);
                    float r0 = sigmoidf_(gir.x + ghr0);
                    float r1 = sigmoidf_(gir.y + ghr1);
                    float z0 = sigmoidf_(giz.x + ghz0);
                    float z1 = sigmoidf_(giz.y + ghz1);
                    float n0 = tanhf(gin.x + r0 * ghn0);
                    float n1 = tanhf(gin.y + r1 * ghn1);
                    h0 = (1.f - z0) * n0 + z0 * h0;
                    h1 = (1.f - z1) * n1 + z1 * h1;
                }
                *(__half2*)(hout + (size_t)row * LAT_ + j0) = __floats2half2_rn(h0, h1);
            }
        }
    }
}

// ---------------- value head ----------------
__global__ __launch_bounds__(256)
void vnet_kernel(const __half* __restrict__ enc, const float* __restrict__ Wv,
                 const float* __restrict__ bv, float* __restrict__ out)
{
    __shared__ float red[8];
    const int b = blockIdx.x;
    float s = 0.f;
    for (int k = threadIdx.x; k < ENC_; k += 256)
        s = fmaf(__half2float(enc[(size_t)b * ENC_ + k]), Wv[k], s);
    #pragma unroll
    for (int o = 16; o > 0; o >>= 1) s += __shfl_down_sync(0xffffffff, s, o);
    if ((threadIdx.x & 31) == 0) red[threadIdx.x >> 5] = s;
    __syncthreads();
    if (threadIdx.x == 0) {
        float tot = 0.f;
        #pragma unroll
        for (int w = 0; w < 8; w++) tot += red[w];
        out[b] = tanhf(tot + bv[0]);
    }
}

// ---------------- probs head (reads h through perm) ----------------
__global__ __launch_bounds__(256)
void probs_kernel(const __half* __restrict__ h, const int* __restrict__ perm,
                  const float* __restrict__ Wpr, const float* __restrict__ bpr,
                  float* __restrict__ out)
{
    __shared__ float Ws[ACT_][LAT_];
    for (int i = threadIdx.x; i < ACT_ * LAT_; i += 256)
        Ws[i / LAT_][i % LAT_] = Wpr[i];
    __syncthreads();

    const int warp = threadIdx.x >> 5;
    const int lane = threadIdx.x & 31;
    const int b = blockIdx.x * 8 + warp;

    float a0 = 0.f, a1 = 0.f, a2 = 0.f;
    const __half* hb = h + (size_t)perm[b] * LAT_;
    for (int k = lane; k < LAT_; k += 32) {
        float hv = __half2float(hb[k]);
        a0 = fmaf(hv, Ws[0][k], a0);
        a1 = fmaf(hv, Ws[1][k], a1);
        a2 = fmaf(hv, Ws[2][k], a2);
    }
    #pragma unroll
    for (int o = 16; o > 0; o >>= 1) {
        a0 += __shfl_down_sync(0xffffffff, a0, o);
        a1 += __shfl_down_sync(0xffffffff, a1, o);
        a2 += __shfl_down_sync(0xffffffff, a2, o);
    }
    if (lane == 0) {
        float l0 = fmaxf(a0 + bpr[0], 0.f);
        float l1 = fmaxf(a1 + bpr[1], 0.f);
        float l2 = fmaxf(a2 + bpr[2], 0.f);
        float m = fmaxf(l0, fmaxf(l1, l2));
        float e0 = expf(l0 - m), e1 = expf(l1 - m), e2 = expf(l2 - m);
        float inv = 1.f / (e0 + e1 + e2);
        out[(size_t)b * ACT_ + 0] = e0 * inv;
        out[(size_t)b * ACT_ + 1] = e1 * inv;
        out[(size_t)b * ACT_ + 2] = e2 * inv;
    }
}

// ---------------- launch ----------------
static inline void half_pass(const float* in, __half* out, size_t n) {
    int n4 = (int)(n / 4);
    to_half_k<<<(n4 + 255) / 256, 256>>>(in, out, n4);
}

extern "C" void kernel_launch(void* const* d_in, const int* in_sizes, int n_in,
                              void* d_out, int out_size)
{
    const float* observation = (const float*)d_in[0];
    const float* neighbors   = (const float*)d_in[1];
    const int*   counts      = (const int*)  d_in[2];
    const float* W_ds  = (const float*)d_in[3];
    const float* b_ds  = (const float*)d_in[4];
    const float* W_pol = (const float*)d_in[5];
    const float* b_pol = (const float*)d_in[6];
    const float* W_v   = (const float*)d_in[7];
    const float* b_v   = (const float*)d_in[8];
    const float* W_ih  = (const float*)d_in[9];
    const float* b_ih  = (const float*)d_in[10];
    const float* W_hh  = (const float*)d_in[11];
    const float* b_hh  = (const float*)d_in[12];
    const float* W_pr  = (const float*)d_in[13];
    const float* b_pr  = (const float*)d_in[14];

    float* out_probs = (float*)d_out;
    float* out_vals  = (float*)d_out + (size_t)B_ * ACT_;

    __half *enc, *h0, *h1, *obs_h, *nb_c, *Wds_h, *Wpol_h, *Wih_h, *Whp;
    float *gi, *bhp;
    int *offs, *Mc, *perm, *order, *cnt_s, *base_s, *active;
    cudaGetSymbolAddress((void**)&enc,   g_enc);
    cudaGetSymbolAddress((void**)&h0,    g_h0);
    cudaGetSymbolAddress((void**)&h1,    g_h1);
    cudaGetSymbolAddress((void**)&gi,    g_gi);
    cudaGetSymbolAddress((void**)&obs_h, g_obs_h);
    cudaGetSymbolAddress((void**)&nb_c,  g_nb_c);
    cudaGetSymbolAddress((void**)&Wds_h, g_Wds_h);
    cudaGetSymbolAddress((void**)&Wpol_h,g_Wpol_h);
    cudaGetSymbolAddress((void**)&Wih_h, g_Wih_h);
    cudaGetSymbolAddress((void**)&Whp,   g_Whp);
    cudaGetSymbolAddress((void**)&bhp,   g_bhp);
    cudaGetSymbolAddress((void**)&offs,  g_offs);
    cudaGetSymbolAddress((void**)&Mc,    g_Mc);
    cudaGetSymbolAddress((void**)&perm,  g_perm);
    cudaGetSymbolAddress((void**)&order, g_order);
    cudaGetSymbolAddress((void**)&cnt_s, g_cnt_s);
    cudaGetSymbolAddress((void**)&base_s,g_base_s);
    cudaGetSymbolAddress((void**)&active,g_active);

    cudaFuncSetAttribute(gemm_h<0,0,1,0>, cudaFuncAttributeMaxDynamicSharedMemorySize, SMEM_BYTES);
    cudaFuncSetAttribute(gemm_h<1,1,0,0>, cudaFuncAttributeMaxDynamicSharedMemorySize, SMEM_BYTES);
    cudaFuncSetAttribute(gemm_h<1,1,0,1>, cudaFuncAttributeMaxDynamicSharedMemorySize, SMEM_BYTES);
    cudaFuncSetAttribute(gru_step, cudaFuncAttributeMaxDynamicSharedMemorySize, GS_SMEM);

    // 0) prep
    scan_counts<<<1, 1024>>>(counts, offs, Mc);
    sort_counts<<<1, 1024>>>(counts, perm, order, active);
    fill_sorted<<<B_ / 256, 256>>>(order, counts, offs, cnt_s, base_s);
    gather_nb<<<B_, 256>>>(neighbors, counts, offs, nb_c);
    half_pass(observation, obs_h, (size_t)B_ * OBS_);
    half_pass(W_ds,  Wds_h,  (size_t)ENC_ * OBS_);
    half_pass(W_pol, Wpol_h, (size_t)LAT_ * ENC_);
    half_pass(W_ih,  Wih_h,  (size_t)L3_ * LAT_);
    permute_whh<<<L3_ / 8, 256>>>(W_hh, b_hh, Whp, bhp);

    // 1) enc = relu(obs @ W_ds^T + b_ds)
    gemm_h<1,1,0,0><<<dim3(ENC_ / 128, B_ / 128), 256, SMEM_BYTES>>>(obs_h, Wds_h, b_ds, enc, ENC_, OBS_, nullptr, nullptr);

    // 2) h0(sorted) = relu(enc @ W_pol^T + b_pol), scattered via perm
    gemm_h<1,1,0,1><<<dim3(LAT_ / 128, B_ / 128), 256, SMEM_BYTES>>>(enc, Wpol_h, b_pol, h0, LAT_, ENC_, nullptr, perm);

    // 3) state_vals
    vnet_kernel<<<B_, 256>>>(enc, W_v, b_v, out_vals);

    // 4) gi over compacted rows
    gemm_h<0,0,1,0><<<dim3(L3_ / 128, (B_ * NMAX_) / 128), 256, SMEM_BYTES>>>(nb_c, Wih_h, b_ih, gi, L3_, LAT_, Mc, nullptr);

    // 5) fused GRU steps on sorted rows (active prefix shrinks with t)
    for (int t = 0; t < NMAX_; t++) {
        const __half* hi = (t & 1) ? h1 : h0;
        __half* ho       = (t & 1) ? h0 : h1;
        gru_step<<<dim3(8, 32), 256, GS_SMEM>>>(hi, Whp, bhp, gi, cnt_s, base_s, active, ho, t);
    }

    // 6) probs (final h in h0, sorted space)
    probs_kernel<<<B_ / 8, 256>>>(h0, perm, W_pr, b_pr, out_probs);
}